// round 13
// baseline (speedup 1.0000x reference)
#include <cuda_runtime.h>
#include <cuda_bf16.h>
#include <stdint.h>
#include <math.h>

#define DD   128
#define NU   40000
#define NTOT 80000
#define EMP  640000
#define EUI  1600000
#define BSZ  8192
#define ATT_BLOCKS 313
#define SST 136

// ------------------------- static device scratch ----------------------------
__device__ float d_h[2 * NU * DD];
__device__ float d_z[2 * NU * DD];
__device__ __nv_bfloat16 d_zh[2 * NU * DD];
__device__ __nv_bfloat16 d_w1h[DD * DD];
__device__ float d_x[2 * NTOT * DD];
__device__ float d_emb[2 * NU * DD];
__device__ float d_rout[4 * NU];
__device__ float d_rin[4 * NU];
__device__ int   d_deg[8 * NU];
__device__ int   d_off[4 * (NU + 1)];
__device__ int   d_cur[4 * NU];
__device__ int   d_csr[4 * EMP];
__device__ int   d_cntui[NTOT];
__device__ float d_dinv[NTOT];
__device__ int   d_offui[NTOT + 1];
__device__ int   d_curui[NTOT];
__device__ int   d_csrui[EUI];
__device__ float d_att[2 * DD];
__device__ float d_beta[2];
__device__ __nv_bfloat16 d_n1h[2 * BSZ * DD];
__device__ __nv_bfloat16 d_n2h[2 * BSZ * DD];
__device__ float d_alls[2 * BSZ];
__device__ float d_dpos[2 * BSZ];
__device__ float d_ssl[1];

// ------------------------- mma helpers --------------------------------------
__device__ __forceinline__ uint32_t smem_u32(const void* p) {
    return (uint32_t)__cvta_generic_to_shared(const_cast<void*>(p));
}
__device__ __forceinline__ void ldmx4(uint32_t* r, uint32_t a) {
    asm volatile("ldmatrix.sync.aligned.m8n8.x4.shared.b16 {%0,%1,%2,%3}, [%4];"
        : "=r"(r[0]), "=r"(r[1]), "=r"(r[2]), "=r"(r[3]) : "r"(a));
}
__device__ __forceinline__ void mma_bf16(float* c, const uint32_t* a, const uint32_t* b) {
    asm volatile(
        "mma.sync.aligned.m16n8k16.row.col.f32.bf16.bf16.f32 "
        "{%0,%1,%2,%3},{%4,%5,%6,%7},{%8,%9},{%0,%1,%2,%3};"
        : "+f"(c[0]), "+f"(c[1]), "+f"(c[2]), "+f"(c[3])
        : "r"(a[0]), "r"(a[1]), "r"(a[2]), "r"(a[3]), "r"(b[0]), "r"(b[1]));
}

// ------------------------- small utilities ----------------------------------
__global__ void k_zero_i(int* p, int n) {
    int i = blockIdx.x * blockDim.x + threadIdx.x;
    if (i < n) p[i] = 0;
}
__global__ void k_zero_f(float* p, int n) {
    int i = blockIdx.x * blockDim.x + threadIdx.x;
    if (i < n) p[i] = 0.f;
}
// all 8 metapath degree counts in one launch; 4 edges per thread via int4
__global__ void k_count_mp(const int* s0, const int* d0, const int* s1, const int* d1,
                           const int* s2, const int* d2, const int* s3, const int* d3,
                           int* deg) {
    const int Q = EMP / 4;   // int4 groups per segment
    int t = blockIdx.x * blockDim.x + threadIdx.x;
    if (t >= 8 * Q) return;
    int seg = t / Q;
    int o = (t - seg * Q) * 4;
    const int* arr;
    int* cnt;
    switch (seg) {
        case 0: arr = s0; cnt = deg + 0 * NU; break;
        case 1: arr = d0; cnt = deg + 4 * NU; break;
        case 2: arr = s1; cnt = deg + 1 * NU; break;
        case 3: arr = d1; cnt = deg + 5 * NU; break;
        case 4: arr = s2; cnt = deg + 2 * NU; break;
        case 5: arr = d2; cnt = deg + 6 * NU; break;
        case 6: arr = s3; cnt = deg + 3 * NU; break;
        default: arr = d3; cnt = deg + 7 * NU; break;
    }
    int4 v = *(const int4*)(arr + o);
    atomicAdd(&cnt[v.x], 1);
    atomicAdd(&cnt[v.y], 1);
    atomicAdd(&cnt[v.z], 1);
    atomicAdd(&cnt[v.w], 1);
}
__global__ void k_count_ui(const int* __restrict__ ids, int* __restrict__ cnt) {
    int t = blockIdx.x * blockDim.x + threadIdx.x;
    if (t >= EUI / 4) return;
    int4 v = *(const int4*)(ids + t * 4);
    atomicAdd(&cnt[v.x], 1);
    atomicAdd(&cnt[v.y], 1);
    atomicAdd(&cnt[v.z], 1);
    atomicAdd(&cnt[v.w], 1);
}
// fused: rout/rin over 4*NU, dinv over NTOT
__global__ void k_prep(const int* __restrict__ deg, float* __restrict__ rout,
                       float* __restrict__ rin, const int* __restrict__ cntui,
                       float* __restrict__ dinv) {
    int i = blockIdx.x * blockDim.x + threadIdx.x;
    if (i < 4 * NU) {
        rout[i] = rsqrtf(fmaxf((float)deg[i], 1.f));
        rin[i]  = rsqrtf(fmaxf((float)deg[4 * NU + i], 1.f));
    }
    if (i < NTOT) {
        int c = cntui[i];
        dinv[i] = (c > 0) ? rsqrtf((float)c) : 0.f;
    }
}
__global__ void k_scan(const int* __restrict__ cnt, int* __restrict__ off,
                       int* __restrict__ cur, int n) {
    __shared__ int part[1024];
    int t = threadIdx.x;
    int chunk = (n + 1023) >> 10;
    int base = t * chunk;
    int s = 0;
    for (int i = 0; i < chunk; i++) {
        int g = base + i;
        if (g < n) s += cnt[g];
    }
    part[t] = s;
    __syncthreads();
    for (int o = 1; o < 1024; o <<= 1) {
        int v = (t >= o) ? part[t - o] : 0;
        __syncthreads();
        part[t] += v;
        __syncthreads();
    }
    int run = (t == 0) ? 0 : part[t - 1];
    for (int i = 0; i < chunk; i++) {
        int g = base + i;
        if (g < n) { off[g] = run; cur[g] = run; run += cnt[g]; }
    }
    if (t == 0) off[n] = part[1023];
}
// 4 metapath fills in one launch (path = blockIdx.y)
__global__ void k_fill_mp(const int* k0, const int* v0, const int* k1, const int* v1,
                          const int* k2, const int* v2, const int* k3, const int* v3,
                          int* cur, int* csr) {
    int path = blockIdx.y;
    int i = blockIdx.x * blockDim.x + threadIdx.x;
    if (i >= EMP) return;
    const int* key;
    const int* val;
    switch (path) {
        case 0: key = k0; val = v0; break;
        case 1: key = k1; val = v1; break;
        case 2: key = k2; val = v2; break;
        default: key = k3; val = v3; break;
    }
    int slot = atomicAdd(&cur[path * NU + key[i]], 1);
    csr[(size_t)path * EMP + slot] = val[i];
}
__global__ void k_fill(const int* __restrict__ key, const int* __restrict__ val,
                       int n, int* __restrict__ cur, int* __restrict__ csr) {
    int i = blockIdx.x * blockDim.x + threadIdx.x;
    if (i < n) {
        int slot = atomicAdd(&cur[key[i]], 1);
        csr[slot] = val[i];
    }
}
__global__ void k_cvtW(const float* __restrict__ W, __nv_bfloat16* __restrict__ Wh) {
    int i = blockIdx.x * blockDim.x + threadIdx.x;
    if (i < DD * DD) {
        int k = i >> 7, nn = i & 127;
        Wh[nn * DD + k] = __float2bfloat16(W[i]);  // [n][k]
    }
}

// ------------------------- pull-style graph conv ----------------------------
// warp per destination row; lanes cooperatively fetch 32 edge ids + scales
// (one coalesced L2 trip per 32 edges), then shfl-broadcast and stream the
// h-row gathers with high MLP. path = blockIdx.y with explicit strides.
__global__ void __launch_bounds__(256) k_pull(
        const float* __restrict__ h, const float* __restrict__ rout,
        const float* __restrict__ rin, const int* __restrict__ off,
        const int* __restrict__ csr, float* __restrict__ z,
        __nv_bfloat16* __restrict__ zh, int n,
        int nodeStride, int offStride, int edgeStride, int featStride)
{
    int path = blockIdx.y;
    rout += (size_t)path * nodeStride;
    rin  += (size_t)path * nodeStride;
    off  += (size_t)path * offStride;
    csr  += (size_t)path * edgeStride;
    z    += (size_t)path * featStride;
    if (zh) zh += (size_t)path * featStride;

    int gid = blockIdx.x * blockDim.x + threadIdx.x;
    int v = gid >> 5;
    if (v >= n) return;
    int lane = gid & 31;
    int col = lane << 2;
    int j0 = off[v], jend = off[v + 1];
    float ax = 0.f, ay = 0.f, az = 0.f, aw = 0.f;
    for (int base = j0; base < jend; base += 32) {
        int cnt = jend - base;
        if (cnt > 32) cnt = 32;
        int sidx = 0;
        float srv = 0.f;
        if (lane < cnt) {
            sidx = __ldg(csr + base + lane);
            srv = __ldg(rout + sidx);
        }
#pragma unroll 8
        for (int e = 0; e < cnt; e++) {
            int s = __shfl_sync(0xffffffffu, sidx, e);
            float rv = __shfl_sync(0xffffffffu, srv, e);
            float4 hv = *(const float4*)(h + (size_t)s * DD + col);
            ax = fmaf(hv.x, rv, ax);
            ay = fmaf(hv.y, rv, ay);
            az = fmaf(hv.z, rv, az);
            aw = fmaf(hv.w, rv, aw);
        }
    }
    float ri = rin[v];
    float4 o;
    o.x = ax * ri; o.y = ay * ri; o.z = az * ri; o.w = aw * ri;
    *(float4*)(z + (size_t)v * DD + col) = o;
    if (zh) {
        __nv_bfloat162 p0 = __floats2bfloat162_rn(o.x, o.y);
        __nv_bfloat162 p1 = __floats2bfloat162_rn(o.z, o.w);
        uint2 w;
        w.x = *(uint32_t*)&p0;
        w.y = *(uint32_t*)&p1;
        *(uint2*)(zh + (size_t)v * DD + col) = w;
    }
}

// ------------- semantic attention via tensor cores --------------------------
__global__ void __launch_bounds__(256) k_att2(
        const __nv_bfloat16* __restrict__ zh_all,
        const __nv_bfloat16* __restrict__ w1h,
        const float* __restrict__ b1, float* __restrict__ attsum, int n)
{
    extern __shared__ __nv_bfloat16 smh[];
    __nv_bfloat16* As = smh;
    __nv_bfloat16* Bs = smh + 128 * SST;
    __shared__ float sred[DD];
    int t = threadIdx.x;
    int path = blockIdx.x / ATT_BLOCKS;
    int blk = blockIdx.x % ATT_BLOCKS;
    const __nv_bfloat16* zh = zh_all + (size_t)path * NU * DD;
    float* att = attsum + path * DD;
    int row0 = blk * 128;
    if (t < DD) sred[t] = 0.f;
    for (int i = t; i < 2048; i += 256) {
        int r = i >> 4, c = i & 15;
        uint4 v = make_uint4(0, 0, 0, 0);
        if (row0 + r < n) v = *(const uint4*)(zh + (size_t)(row0 + r) * DD + c * 8);
        *(uint4*)(As + r * SST + c * 8) = v;
        *(uint4*)(Bs + r * SST + c * 8) = *(const uint4*)(w1h + (size_t)r * DD + c * 8);
    }
    __syncthreads();
    int warp = t >> 5, lane = t & 31;
    int wm = warp >> 1, wn = warp & 1;
    float acc[2][8][4] = {};
    uint32_t a_base = smem_u32(As + (wm * 32 + (lane & 15)) * SST + (lane >> 4) * 8);
    uint32_t b_base = smem_u32(Bs + (wn * 64 + (lane >> 4) * 8 + (lane & 7)) * SST +
                               ((lane >> 3) & 1) * 8);
#pragma unroll
    for (int ks = 0; ks < 8; ks++) {
        uint32_t a[2][4], b[4][4];
        ldmx4(a[0], a_base + ks * 32);
        ldmx4(a[1], a_base + 16 * SST * 2 + ks * 32);
#pragma unroll
        for (int p = 0; p < 4; p++)
            ldmx4(b[p], b_base + p * 16 * SST * 2 + ks * 32);
#pragma unroll
        for (int mi = 0; mi < 2; mi++)
#pragma unroll
            for (int nt = 0; nt < 8; nt++)
                mma_bf16(acc[mi][nt], a[mi], &b[nt >> 1][(nt & 1) * 2]);
    }
    float b1v[8][2];
#pragma unroll
    for (int nt = 0; nt < 8; nt++) {
        int col = wn * 64 + nt * 8 + 2 * (lane & 3);
        b1v[nt][0] = __ldg(b1 + col);
        b1v[nt][1] = __ldg(b1 + col + 1);
    }
    float cs[8][2] = {};
    int r_lo = row0 + wm * 32 + (lane >> 2);
#pragma unroll
    for (int mi = 0; mi < 2; mi++) {
        int ra = r_lo + mi * 16, rb = ra + 8;
        bool va = ra < n, vb = rb < n;
#pragma unroll
        for (int nt = 0; nt < 8; nt++) {
            if (va) {
                cs[nt][0] += tanhf(acc[mi][nt][0] + b1v[nt][0]);
                cs[nt][1] += tanhf(acc[mi][nt][1] + b1v[nt][1]);
            }
            if (vb) {
                cs[nt][0] += tanhf(acc[mi][nt][2] + b1v[nt][0]);
                cs[nt][1] += tanhf(acc[mi][nt][3] + b1v[nt][1]);
            }
        }
    }
#pragma unroll
    for (int o = 4; o <= 16; o <<= 1)
#pragma unroll
        for (int nt = 0; nt < 8; nt++) {
            cs[nt][0] += __shfl_xor_sync(0xffffffffu, cs[nt][0], o);
            cs[nt][1] += __shfl_xor_sync(0xffffffffu, cs[nt][1], o);
        }
    if (lane < 4) {
#pragma unroll
        for (int nt = 0; nt < 8; nt++) {
            int col = wn * 64 + nt * 8 + 2 * lane;
            atomicAdd(&sred[col], cs[nt][0]);
            atomicAdd(&sred[col + 1], cs[nt][1]);
        }
    }
    __syncthreads();
    if (t < DD) atomicAdd(&att[t], sred[t]);
}

__global__ void k_beta(const float* __restrict__ W2, int n) {
    float w0 = 0.f, w1 = 0.f;
    for (int k = 0; k < DD; k++) {
        w0 += d_att[k] * W2[k];
        w1 += d_att[DD + k] * W2[k];
    }
    float inv = 1.f / (float)n;
    w0 *= inv; w1 *= inv;
    float m = fmaxf(w0, w1);
    float e0 = expf(w0 - m), e1 = expf(w1 - m);
    float den = 1.f / (e0 + e1);
    d_beta[0] = e0 * den;
    d_beta[1] = e1 * den;
}

__global__ void k_combine(const float* __restrict__ z, float* __restrict__ h, int n) {
    int i = blockIdx.x * blockDim.x + threadIdx.x;
    if (i < n) h[i] = d_beta[0] * z[i] + d_beta[1] * z[i + NU * DD];
}

__global__ void k_emb(const float* __restrict__ xf, int n) {
    int i = blockIdx.x * blockDim.x + threadIdx.x;
    if (i < n) {
        d_emb[i]           = 0.5f * (d_h[i] + xf[i]);
        d_emb[NU * DD + i] = 0.5f * (d_h[NU * DD + i] + xf[NU * DD + i]);
    }
}

// ------------------------- SSL ----------------------------------------------
// both slots in one launch (slot = blockIdx.y)
__global__ void __launch_bounds__(256) k_norm(
        const float* __restrict__ e1base, const float* __restrict__ e2base,
        const int* __restrict__ idx0, const int* __restrict__ idx1)
{
    int slot = blockIdx.y;
    const float* e1b = e1base + (size_t)slot * NU * DD;
    const float* e2b = e2base + (size_t)slot * NU * DD;
    const int* idx = slot ? idx1 : idx0;
    int gid = blockIdx.x * blockDim.x + threadIdx.x;
    int r = gid >> 5;
    if (r >= BSZ) return;
    int lane = gid & 31;
    int row = idx[r];
    float4 a = *(const float4*)(e1b + (size_t)row * DD + lane * 4);
    float4 b = *(const float4*)(e2b + (size_t)row * DD + lane * 4);
    float s11 = a.x * a.x + a.y * a.y + a.z * a.z + a.w * a.w;
    float s22 = b.x * b.x + b.y * b.y + b.z * b.z + b.w * b.w;
    float s12 = a.x * b.x + a.y * b.y + a.z * b.z + a.w * b.w;
    for (int o = 16; o; o >>= 1) {
        s11 += __shfl_xor_sync(0xffffffffu, s11, o);
        s22 += __shfl_xor_sync(0xffffffffu, s22, o);
        s12 += __shfl_xor_sync(0xffffffffu, s12, o);
    }
    float i1 = 1.f / fmaxf(sqrtf(s11), 1e-12f);
    float i2 = 1.f / fmaxf(sqrtf(s22), 1e-12f);
    if (lane == 0) d_dpos[slot * BSZ + r] = s12 * i1 * i2;
    __nv_bfloat162 na0 = __floats2bfloat162_rn(a.x * i1, a.y * i1);
    __nv_bfloat162 na1 = __floats2bfloat162_rn(a.z * i1, a.w * i1);
    __nv_bfloat162 nb0 = __floats2bfloat162_rn(b.x * i2, b.y * i2);
    __nv_bfloat162 nb1 = __floats2bfloat162_rn(b.z * i2, b.w * i2);
    uint2 wa, wb;
    wa.x = *(uint32_t*)&na0; wa.y = *(uint32_t*)&na1;
    wb.x = *(uint32_t*)&nb0; wb.y = *(uint32_t*)&nb1;
    size_t base = (size_t)slot * BSZ * DD + (size_t)r * DD + lane * 4;
    *(uint2*)(d_n1h + base) = wa;
    *(uint2*)(d_n2h + base) = wb;
}

__device__ __forceinline__ float fast_exp(float x) {
    float y = x * 1.4426950408889634f;
    float nf = rintf(y);
    float f = y - nf;
    float p = 1.5403530e-4f;
    p = fmaf(p, f, 1.3333558e-3f);
    p = fmaf(p, f, 9.6181291e-3f);
    p = fmaf(p, f, 5.5504109e-2f);
    p = fmaf(p, f, 2.4022651e-1f);
    p = fmaf(p, f, 6.9314718e-1f);
    p = fmaf(p, f, 1.0f);
    return p * __int_as_float(((int)nf + 127) << 23);
}

__global__ void __launch_bounds__(256) k_sslgemm_mma()
{
    extern __shared__ __nv_bfloat16 smh[];
    __nv_bfloat16* As = smh;
    __nv_bfloat16* Bs = smh + 128 * SST;
    __shared__ float sred[128];
    int t = threadIdx.x;
    int slot = blockIdx.z;
    int rowA0 = blockIdx.y * 128, colB0 = blockIdx.x * 128;
    const __nv_bfloat16* n1 = d_n1h + (size_t)slot * BSZ * DD;
    const __nv_bfloat16* n2 = d_n2h + (size_t)slot * BSZ * DD;
    if (t < 128) sred[t] = 0.f;
    for (int i = t; i < 2048; i += 256) {
        int r = i >> 4, c = i & 15;
        *(uint4*)(As + r * SST + c * 8) = *(const uint4*)(n1 + (size_t)(rowA0 + r) * DD + c * 8);
        *(uint4*)(Bs + r * SST + c * 8) = *(const uint4*)(n2 + (size_t)(colB0 + r) * DD + c * 8);
    }
    __syncthreads();
    int warp = t >> 5, lane = t & 31;
    int wm = warp >> 1, wn = warp & 1;
    float acc[2][8][4] = {};
    uint32_t a_base = smem_u32(As + (wm * 32 + (lane & 15)) * SST + (lane >> 4) * 8);
    uint32_t b_base = smem_u32(Bs + (wn * 64 + (lane >> 4) * 8 + (lane & 7)) * SST +
                               ((lane >> 3) & 1) * 8);
#pragma unroll
    for (int ks = 0; ks < 8; ks++) {
        uint32_t a[2][4], b[4][4];
        ldmx4(a[0], a_base + ks * 32);
        ldmx4(a[1], a_base + 16 * SST * 2 + ks * 32);
#pragma unroll
        for (int p = 0; p < 4; p++)
            ldmx4(b[p], b_base + p * 16 * SST * 2 + ks * 32);
#pragma unroll
        for (int mi = 0; mi < 2; mi++)
#pragma unroll
            for (int nt = 0; nt < 8; nt++)
                mma_bf16(acc[mi][nt], a[mi], &b[nt >> 1][(nt & 1) * 2]);
    }
    float rs[2][2] = {};
#pragma unroll
    for (int mi = 0; mi < 2; mi++)
#pragma unroll
        for (int nt = 0; nt < 8; nt++) {
            rs[mi][0] += fast_exp(2.f * acc[mi][nt][0]) + fast_exp(2.f * acc[mi][nt][1]);
            rs[mi][1] += fast_exp(2.f * acc[mi][nt][2]) + fast_exp(2.f * acc[mi][nt][3]);
        }
#pragma unroll
    for (int o = 1; o <= 2; o <<= 1) {
        rs[0][0] += __shfl_xor_sync(0xffffffffu, rs[0][0], o);
        rs[0][1] += __shfl_xor_sync(0xffffffffu, rs[0][1], o);
        rs[1][0] += __shfl_xor_sync(0xffffffffu, rs[1][0], o);
        rs[1][1] += __shfl_xor_sync(0xffffffffu, rs[1][1], o);
    }
    if ((lane & 3) == 0) {
        int r0 = wm * 32 + (lane >> 2);
        atomicAdd(&sred[r0],      rs[0][0]);
        atomicAdd(&sred[r0 + 8],  rs[0][1]);
        atomicAdd(&sred[r0 + 16], rs[1][0]);
        atomicAdd(&sred[r0 + 24], rs[1][1]);
    }
    __syncthreads();
    if (t < 128) atomicAdd(&d_alls[slot * BSZ + rowA0 + t], sred[t]);
}

__global__ void k_sslreduce(float scale) {
    __shared__ float sp[256];
    int t = threadIdx.x;
    float s = 0.f;
    for (int i = t; i < 2 * BSZ; i += 256)
        s += logf(d_alls[i]) - 2.f * d_dpos[i];
    sp[t] = s;
    __syncthreads();
    for (int o = 128; o; o >>= 1) {
        if (t < o) sp[t] += sp[t + o];
        __syncthreads();
    }
    if (t == 0) d_ssl[0] = sp[0] * scale;
}

__global__ void k_writeloss(float* dst) { *dst = d_ssl[0]; }

// ------------- final: out = LN(relu(emb[idx] @ W + b)) ----------------------
__global__ void __launch_bounds__(256) k_final(
        const float* __restrict__ embb, const int* __restrict__ idx,
        const float* __restrict__ W, const float* __restrict__ bias,
        const float* __restrict__ lng, const float* __restrict__ lnb,
        float* __restrict__ outb)
{
    extern __shared__ float smf[];
    float* Ws = smf;
    float* Zs = smf + 16384;
    int t = threadIdx.x;
    for (int i = t; i < 4096; i += 256)
        ((float4*)Ws)[i] = ((const float4*)W)[i];
    __syncthreads();
    int warp = t >> 5, lane = t & 31;
    int base = (blockIdx.x * 8 + warp) * 4;
    float* zr = Zs + warp * 512;
    for (int i = lane; i < 128; i += 32) {
        int r = i >> 5, c = i & 31;
        ((float4*)zr)[i] = ((const float4*)(embb + (size_t)idx[base + r] * DD))[c];
    }
    __syncwarp();
    float4 bb = ((const float4*)bias)[lane];
    float acc[4][4];
#pragma unroll
    for (int r = 0; r < 4; r++) {
        acc[r][0] = bb.x; acc[r][1] = bb.y; acc[r][2] = bb.z; acc[r][3] = bb.w;
    }
#pragma unroll 4
    for (int k = 0; k < DD; k++) {
        float4 w = *(const float4*)(Ws + k * DD + lane * 4);
        float zv[4];
        zv[0] = zr[k]; zv[1] = zr[DD + k]; zv[2] = zr[2 * DD + k]; zv[3] = zr[3 * DD + k];
#pragma unroll
        for (int r = 0; r < 4; r++) {
            acc[r][0] = fmaf(zv[r], w.x, acc[r][0]);
            acc[r][1] = fmaf(zv[r], w.y, acc[r][1]);
            acc[r][2] = fmaf(zv[r], w.z, acc[r][2]);
            acc[r][3] = fmaf(zv[r], w.w, acc[r][3]);
        }
    }
    float4 g4 = ((const float4*)lng)[lane];
    float4 lb4 = ((const float4*)lnb)[lane];
#pragma unroll
    for (int r = 0; r < 4; r++) {
        float v0 = fmaxf(acc[r][0], 0.f), v1 = fmaxf(acc[r][1], 0.f);
        float v2 = fmaxf(acc[r][2], 0.f), v3 = fmaxf(acc[r][3], 0.f);
        float s = v0 + v1 + v2 + v3;
        for (int o = 16; o; o >>= 1) s += __shfl_xor_sync(0xffffffffu, s, o);
        float mu = s * (1.f / 128.f);
        float w0 = v0 - mu, w1 = v1 - mu, w2 = v2 - mu, w3 = v3 - mu;
        float q = w0 * w0 + w1 * w1 + w2 * w2 + w3 * w3;
        for (int o = 16; o; o >>= 1) q += __shfl_xor_sync(0xffffffffu, q, o);
        float inv = rsqrtf(q * (1.f / 128.f) + 1e-5f);
        float4 ov;
        ov.x = w0 * inv * g4.x + lb4.x;
        ov.y = w1 * inv * g4.y + lb4.y;
        ov.z = w2 * inv * g4.z + lb4.z;
        ov.w = w3 * inv * g4.w + lb4.w;
        *(float4*)(outb + (size_t)(base + r) * DD + lane * 4) = ov;
    }
}

// ------------------------- host orchestration -------------------------------
extern "C" void kernel_launch(void* const* d_in, const int* in_sizes, int n_in,
                              void* d_out, int out_size)
{
    const float* feat_user = (const float*)d_in[0];
    const float* feat_item = (const float*)d_in[1];
    const float* u_W1 = (const float*)d_in[2];
    const float* u_b1 = (const float*)d_in[3];
    const float* u_W2 = (const float*)d_in[4];
    const float* i_W1 = (const float*)d_in[5];
    const float* i_b1 = (const float*)d_in[6];
    const float* i_W2 = (const float*)d_in[7];
    const float* user_W = (const float*)d_in[8];
    const float* user_b = (const float*)d_in[9];
    const float* item_W = (const float*)d_in[10];
    const float* item_b = (const float*)d_in[11];
    const float* ln_g = (const float*)d_in[12];
    const float* ln_b = (const float*)d_in[13];
    const int* mpsrc[4] = {(const int*)d_in[14], (const int*)d_in[16],
                           (const int*)d_in[18], (const int*)d_in[20]};
    const int* mpdst[4] = {(const int*)d_in[15], (const int*)d_in[17],
                           (const int*)d_in[19], (const int*)d_in[21]};
    const int* ui_row = (const int*)d_in[22];
    const int* ui_col = (const int*)d_in[23];
    const int* user_idx = (const int*)d_in[24];
    const int* item_idx = (const int*)d_in[25];
    const int* neg_idx = (const int*)d_in[26];
    float* out = (float*)d_out;

    float *p_h, *p_z, *p_x, *p_emb, *p_rout, *p_rin, *p_dinv, *p_att, *p_alls;
    int *p_deg, *p_off, *p_cur, *p_csr, *p_cntui, *p_offui, *p_curui, *p_csrui;
    __nv_bfloat16 *p_zh, *p_w1h;
    cudaGetSymbolAddress((void**)&p_h, d_h);
    cudaGetSymbolAddress((void**)&p_z, d_z);
    cudaGetSymbolAddress((void**)&p_zh, d_zh);
    cudaGetSymbolAddress((void**)&p_w1h, d_w1h);
    cudaGetSymbolAddress((void**)&p_x, d_x);
    cudaGetSymbolAddress((void**)&p_emb, d_emb);
    cudaGetSymbolAddress((void**)&p_rout, d_rout);
    cudaGetSymbolAddress((void**)&p_rin, d_rin);
    cudaGetSymbolAddress((void**)&p_dinv, d_dinv);
    cudaGetSymbolAddress((void**)&p_att, d_att);
    cudaGetSymbolAddress((void**)&p_alls, d_alls);
    cudaGetSymbolAddress((void**)&p_deg, d_deg);
    cudaGetSymbolAddress((void**)&p_off, d_off);
    cudaGetSymbolAddress((void**)&p_cur, d_cur);
    cudaGetSymbolAddress((void**)&p_csr, d_csr);
    cudaGetSymbolAddress((void**)&p_cntui, d_cntui);
    cudaGetSymbolAddress((void**)&p_offui, d_offui);
    cudaGetSymbolAddress((void**)&p_curui, d_curui);
    cudaGetSymbolAddress((void**)&p_csrui, d_csrui);

    const int T = 256;
    const int GEMM_SMEM = 2 * 128 * SST * 2;
    cudaFuncSetAttribute(k_att2, cudaFuncAttributeMaxDynamicSharedMemorySize, GEMM_SMEM);
    cudaFuncSetAttribute(k_sslgemm_mma, cudaFuncAttributeMaxDynamicSharedMemorySize, GEMM_SMEM);
    cudaFuncSetAttribute(k_final, cudaFuncAttributeMaxDynamicSharedMemorySize, 81920);

    // ---- degrees + CSR build ----
    k_zero_i<<<(8 * NU + T - 1) / T, T>>>(p_deg, 8 * NU);
    k_zero_i<<<(NTOT + T - 1) / T, T>>>(p_cntui, NTOT);
    k_count_mp<<<(8 * (EMP / 4) + T - 1) / T, T>>>(
        mpsrc[0], mpdst[0], mpsrc[1], mpdst[1],
        mpsrc[2], mpdst[2], mpsrc[3], mpdst[3], p_deg);
    k_count_ui<<<((EUI / 4) + T - 1) / T, T>>>(ui_row, p_cntui);
    k_prep<<<(4 * NU + T - 1) / T, T>>>(p_deg, p_rout, p_rin, p_cntui, p_dinv);
    for (int p = 0; p < 4; p++)
        k_scan<<<1, 1024>>>(p_deg + (4 + p) * NU, p_off + p * (NU + 1), p_cur + p * NU, NU);
    k_scan<<<1, 1024>>>(p_cntui, p_offui, p_curui, NTOT);
    {
        dim3 gf((EMP + T - 1) / T, 4);
        k_fill_mp<<<gf, T>>>(mpdst[0], mpsrc[0], mpdst[1], mpsrc[1],
                             mpdst[2], mpsrc[2], mpdst[3], mpsrc[3], p_cur, p_csr);
    }
    k_fill<<<(EUI + T - 1) / T, T>>>(ui_row, ui_col, EUI, p_curui, p_csrui);

    // ---- HAN (both sides): both metapaths per launch via gridDim.y=2 ----
    for (int side = 0; side < 2; side++) {
        const float* feat = side ? feat_item : feat_user;
        const float* W1 = side ? i_W1 : u_W1;
        const float* b1 = side ? i_b1 : u_b1;
        const float* W2 = side ? i_W2 : u_W2;
        float* h = p_h + (size_t)side * NU * DD;
        int p0 = side * 2;
        k_cvtW<<<(DD * DD + T - 1) / T, T>>>(W1, p_w1h);
        dim3 gp((NU * 32) / T, 2);
        for (int layer = 0; layer < 3; layer++) {
            const float* hin = layer ? h : feat;
            k_pull<<<gp, T>>>(hin, p_rout + p0 * NU, p_rin + p0 * NU,
                              p_off + p0 * (NU + 1), p_csr + (size_t)p0 * EMP,
                              p_z, p_zh, NU, NU, NU + 1, EMP, NU * DD);
            k_zero_f<<<1, 256>>>(p_att, 2 * DD);
            k_att2<<<2 * ATT_BLOCKS, 256, GEMM_SMEM>>>(p_zh, p_w1h, b1, p_att, NU);
            k_beta<<<1, 1>>>(W2, NU);
            k_combine<<<(NU * DD + T - 1) / T, T>>>(p_z, h, NU * DD);
        }
    }

    // ---- LightGCN (3 hops) ----
    cudaMemcpyAsync(p_x, feat_user, (size_t)NU * DD * sizeof(float),
                    cudaMemcpyDeviceToDevice);
    cudaMemcpyAsync(p_x + (size_t)NU * DD, feat_item, (size_t)NU * DD * sizeof(float),
                    cudaMemcpyDeviceToDevice);
    float* x0 = p_x;
    float* x1 = p_x + (size_t)NTOT * DD;
    dim3 gu((NTOT * 32) / T, 1);
    k_pull<<<gu, T>>>(x0, p_dinv, p_dinv, p_offui, p_csrui, x1,
                      (__nv_bfloat16*)0, NTOT, 0, 0, 0, 0);
    k_pull<<<gu, T>>>(x1, p_dinv, p_dinv, p_offui, p_csrui, x0,
                      (__nv_bfloat16*)0, NTOT, 0, 0, 0, 0);
    k_pull<<<gu, T>>>(x0, p_dinv, p_dinv, p_offui, p_csrui, x1,
                      (__nv_bfloat16*)0, NTOT, 0, 0, 0, 0);
    float* xf = x1;

    // ---- combine embeddings ----
    k_emb<<<(NU * DD + T - 1) / T, T>>>(xf, NU * DD);

    // ---- SSL ----
    {
        dim3 gn((BSZ * 32) / T, 2);
        k_norm<<<gn, T>>>(xf, p_emb, user_idx, item_idx);
    }
    k_zero_f<<<(2 * BSZ + T - 1) / T, T>>>(p_alls, 2 * BSZ);
    dim3 gg(BSZ / 128, BSZ / 128, 2);
    k_sslgemm_mma<<<gg, 256, GEMM_SMEM>>>();
    k_sslreduce<<<1, 256>>>(0.4f / (float)BSZ);
    k_writeloss<<<1, 1>>>(out + (size_t)3 * BSZ * DD);

    // ---- final gather + GEMM + relu + layernorm ----
    k_final<<<BSZ / 32, 256, 81920>>>(p_emb, user_idx, user_W, user_b, ln_g, ln_b, out);
    k_final<<<BSZ / 32, 256, 81920>>>(p_emb + (size_t)NU * DD, item_idx, item_W, item_b,
                                      ln_g, ln_b, out + (size_t)BSZ * DD);
    k_final<<<BSZ / 32, 256, 81920>>>(p_emb + (size_t)NU * DD, neg_idx, item_W, item_b,
                                      ln_g, ln_b, out + (size_t)2 * BSZ * DD);
}

// round 16
// speedup vs baseline: 1.2567x; 1.2567x over previous
#include <cuda_runtime.h>
#include <cuda_bf16.h>
#include <stdint.h>
#include <math.h>

#define DD   128
#define NU   40000
#define NTOT 80000
#define EMP  640000
#define EUI  1600000
#define BSZ  8192
#define ATT_BLOCKS 313
#define SST 136

// ------------------------- static device scratch ----------------------------
__device__ float d_h[2 * NU * DD];
__device__ float d_z[4 * NU * DD];
__device__ __nv_bfloat16 d_zh[4 * NU * DD];
__device__ __nv_bfloat16 d_w1h[2 * DD * DD];
__device__ float d_x[2 * NTOT * DD];
__device__ float d_emb[2 * NU * DD];
__device__ float d_rout[4 * NU];
__device__ float d_rin[4 * NU];
__device__ int   d_deg[8 * NU];
__device__ int   d_off[4 * (NU + 1)];
__device__ int   d_cur[4 * NU];
__device__ int   d_csr[4 * EMP];
__device__ int   d_cntui[NTOT];
__device__ float d_dinv[NTOT];
__device__ int   d_offui[NTOT + 1];
__device__ int   d_curui[NTOT];
__device__ int   d_csrui[EUI];
__device__ float d_att[4 * DD];
__device__ float d_beta[4];
__device__ __nv_bfloat16 d_n1h[2 * BSZ * DD];
__device__ __nv_bfloat16 d_n2h[2 * BSZ * DD];
__device__ float d_alls[2 * BSZ];
__device__ float d_dpos[2 * BSZ];

// ------------------------- math / mma helpers -------------------------------
__device__ __forceinline__ uint32_t smem_u32(const void* p) {
    return (uint32_t)__cvta_generic_to_shared(const_cast<void*>(p));
}
__device__ __forceinline__ void ldmx4(uint32_t* r, uint32_t a) {
    asm volatile("ldmatrix.sync.aligned.m8n8.x4.shared.b16 {%0,%1,%2,%3}, [%4];"
        : "=r"(r[0]), "=r"(r[1]), "=r"(r[2]), "=r"(r[3]) : "r"(a));
}
__device__ __forceinline__ void mma_bf16(float* c, const uint32_t* a, const uint32_t* b) {
    asm volatile(
        "mma.sync.aligned.m16n8k16.row.col.f32.bf16.bf16.f32 "
        "{%0,%1,%2,%3},{%4,%5,%6,%7},{%8,%9},{%0,%1,%2,%3};"
        : "+f"(c[0]), "+f"(c[1]), "+f"(c[2]), "+f"(c[3])
        : "r"(a[0]), "r"(a[1]), "r"(a[2]), "r"(a[3]), "r"(b[0]), "r"(b[1]));
}
__device__ __forceinline__ float tanh_ap(float x) {
    float r;
    asm("tanh.approx.f32 %0, %1;" : "=f"(r) : "f"(x));
    return r;
}
__device__ __forceinline__ float ex2_ap(float x) {
    float r;
    asm("ex2.approx.f32 %0, %1;" : "=f"(r) : "f"(x));
    return r;
}
#define TWO_LOG2E 2.885390081777927f   // 2/ln2 : exp(2x) = ex2(x*TWO_LOG2E)

// ------------------------- CSR build -----------------------------------------
__global__ void k_zero2(int* a, int na, int* b, int nb) {
    int i = blockIdx.x * blockDim.x + threadIdx.x;
    if (i < na) a[i] = 0;
    else if (i < na + nb) b[i - na] = 0;
}
__global__ void k_count_all(const int* s0, const int* d0, const int* s1, const int* d1,
                            const int* s2, const int* d2, const int* s3, const int* d3,
                            const int* uir, int* deg, int* cntui) {
    const int Q = EMP / 4;
    int t = blockIdx.x * blockDim.x + threadIdx.x;
    if (t < 8 * Q) {
        int seg = t / Q;
        int o = (t - seg * Q) * 4;
        const int* arr;
        int* cnt;
        switch (seg) {
            case 0: arr = s0; cnt = deg + 0 * NU; break;
            case 1: arr = d0; cnt = deg + 4 * NU; break;
            case 2: arr = s1; cnt = deg + 1 * NU; break;
            case 3: arr = d1; cnt = deg + 5 * NU; break;
            case 4: arr = s2; cnt = deg + 2 * NU; break;
            case 5: arr = d2; cnt = deg + 6 * NU; break;
            case 6: arr = s3; cnt = deg + 3 * NU; break;
            default: arr = d3; cnt = deg + 7 * NU; break;
        }
        int4 v = *(const int4*)(arr + o);
        atomicAdd(&cnt[v.x], 1);
        atomicAdd(&cnt[v.y], 1);
        atomicAdd(&cnt[v.z], 1);
        atomicAdd(&cnt[v.w], 1);
    } else {
        int u = t - 8 * Q;
        if (u < EUI / 4) {
            int4 v = *(const int4*)(uir + u * 4);
            atomicAdd(&cntui[v.x], 1);
            atomicAdd(&cntui[v.y], 1);
            atomicAdd(&cntui[v.z], 1);
            atomicAdd(&cntui[v.w], 1);
        }
    }
}
__global__ void k_prep(const int* __restrict__ deg, float* __restrict__ rout,
                       float* __restrict__ rin, const int* __restrict__ cntui,
                       float* __restrict__ dinv) {
    int i = blockIdx.x * blockDim.x + threadIdx.x;
    if (i < 4 * NU) {
        rout[i] = rsqrtf(fmaxf((float)deg[i], 1.f));
        rin[i]  = rsqrtf(fmaxf((float)deg[4 * NU + i], 1.f));
    }
    if (i < NTOT) {
        int c = cntui[i];
        dinv[i] = (c > 0) ? rsqrtf((float)c) : 0.f;
    }
}
__global__ void k_scan5() {
    __shared__ int part[1024];
    int b = blockIdx.x;
    const int* cnt;
    int* off;
    int* cur;
    int n;
    if (b < 4) { cnt = d_deg + (4 + b) * NU; off = d_off + b * (NU + 1); cur = d_cur + b * NU; n = NU; }
    else       { cnt = d_cntui; off = d_offui; cur = d_curui; n = NTOT; }
    int t = threadIdx.x;
    int chunk = (n + 1023) >> 10;
    int base = t * chunk;
    int s = 0;
    for (int i = 0; i < chunk; i++) {
        int g = base + i;
        if (g < n) s += cnt[g];
    }
    part[t] = s;
    __syncthreads();
    for (int o = 1; o < 1024; o <<= 1) {
        int v = (t >= o) ? part[t - o] : 0;
        __syncthreads();
        part[t] += v;
        __syncthreads();
    }
    int run = (t == 0) ? 0 : part[t - 1];
    for (int i = 0; i < chunk; i++) {
        int g = base + i;
        if (g < n) { off[g] = run; cur[g] = run; run += cnt[g]; }
    }
    if (t == 0) off[n] = part[1023];
}
__global__ void k_fill_mp(const int* k0, const int* v0, const int* k1, const int* v1,
                          const int* k2, const int* v2, const int* k3, const int* v3,
                          int* cur, int* csr) {
    int path = blockIdx.y;
    int i = blockIdx.x * blockDim.x + threadIdx.x;
    if (i >= EMP) return;
    const int* key;
    const int* val;
    switch (path) {
        case 0: key = k0; val = v0; break;
        case 1: key = k1; val = v1; break;
        case 2: key = k2; val = v2; break;
        default: key = k3; val = v3; break;
    }
    int slot = atomicAdd(&cur[path * NU + key[i]], 1);
    csr[(size_t)path * EMP + slot] = val[i];
}
__global__ void k_fill(const int* __restrict__ key, const int* __restrict__ val,
                       int n, int* __restrict__ cur, int* __restrict__ csr) {
    int i = blockIdx.x * blockDim.x + threadIdx.x;
    if (i < n) {
        int slot = atomicAdd(&cur[key[i]], 1);
        csr[slot] = val[i];
    }
}
__global__ void k_cvtW2(const float* __restrict__ Wu, const float* __restrict__ Wi,
                        __nv_bfloat16* __restrict__ Wh) {
    int i = blockIdx.x * blockDim.x + threadIdx.x;
    if (i < 4 * DD) d_att[i] = 0.f;
    if (i < 2 * DD * DD) {
        int side = i >> 14;
        int r = i & 16383;
        int k = r >> 7, nn = r & 127;
        const float* W = side ? Wi : Wu;
        Wh[side * DD * DD + nn * DD + k] = __float2bfloat16(W[r]);
    }
}

// ------------------------- pull-style graph conv ----------------------------
__global__ void __launch_bounds__(256) k_pull(
        const float* __restrict__ h0, const float* __restrict__ h1, int split,
        const float* __restrict__ rout, const float* __restrict__ rin,
        const int* __restrict__ off, const int* __restrict__ csr,
        float* __restrict__ z, __nv_bfloat16* __restrict__ zh, int n,
        int nodeStride, int offStride, int edgeStride, int featStride)
{
    int path = blockIdx.y;
    rout += (size_t)path * nodeStride;
    rin  += (size_t)path * nodeStride;
    off  += (size_t)path * offStride;
    csr  += (size_t)path * edgeStride;
    z    += (size_t)path * featStride;
    if (zh) zh += (size_t)path * featStride;
    int ofs = (path >> 1) * split;

    int gid = blockIdx.x * blockDim.x + threadIdx.x;
    int v = gid >> 5;
    if (v >= n) return;
    int col = (gid & 31) << 2;
    int j = off[v], jend = off[v + 1];
    float ax = 0.f, ay = 0.f, az = 0.f, aw = 0.f;
    for (; j + 4 <= jend; j += 4) {
        int s0 = csr[j], s1 = csr[j + 1], s2 = csr[j + 2], s3 = csr[j + 3];
        float r0 = __ldg(rout + s0), r1 = __ldg(rout + s1);
        float r2 = __ldg(rout + s2), r3 = __ldg(rout + s3);
        int e0 = s0 + ofs, e1 = s1 + ofs, e2 = s2 + ofs, e3 = s3 + ofs;
        const float* p0 = (e0 < split) ? h0 + (size_t)e0 * DD : h1 + (size_t)(e0 - split) * DD;
        const float* p1 = (e1 < split) ? h0 + (size_t)e1 * DD : h1 + (size_t)(e1 - split) * DD;
        const float* p2 = (e2 < split) ? h0 + (size_t)e2 * DD : h1 + (size_t)(e2 - split) * DD;
        const float* p3 = (e3 < split) ? h0 + (size_t)e3 * DD : h1 + (size_t)(e3 - split) * DD;
        float4 h0v = *(const float4*)(p0 + col);
        float4 h1v = *(const float4*)(p1 + col);
        float4 h2v = *(const float4*)(p2 + col);
        float4 h3v = *(const float4*)(p3 + col);
        ax += h0v.x * r0 + h1v.x * r1 + h2v.x * r2 + h3v.x * r3;
        ay += h0v.y * r0 + h1v.y * r1 + h2v.y * r2 + h3v.y * r3;
        az += h0v.z * r0 + h1v.z * r1 + h2v.z * r2 + h3v.z * r3;
        aw += h0v.w * r0 + h1v.w * r1 + h2v.w * r2 + h3v.w * r3;
    }
    for (; j < jend; j++) {
        int s = csr[j];
        float r = __ldg(rout + s);
        int e = s + ofs;
        const float* p = (e < split) ? h0 + (size_t)e * DD : h1 + (size_t)(e - split) * DD;
        float4 hv = *(const float4*)(p + col);
        ax = fmaf(hv.x, r, ax); ay = fmaf(hv.y, r, ay);
        az = fmaf(hv.z, r, az); aw = fmaf(hv.w, r, aw);
    }
    float ri = rin[v];
    float4 o;
    o.x = ax * ri; o.y = ay * ri; o.z = az * ri; o.w = aw * ri;
    *(float4*)(z + (size_t)v * DD + col) = o;
    if (zh) {
        __nv_bfloat162 q0 = __floats2bfloat162_rn(o.x, o.y);
        __nv_bfloat162 q1 = __floats2bfloat162_rn(o.z, o.w);
        uint2 w;
        w.x = *(uint32_t*)&q0;
        w.y = *(uint32_t*)&q1;
        *(uint2*)(zh + (size_t)v * DD + col) = w;
    }
}

// ------------- semantic attention via tensor cores (4 paths) ----------------
__global__ void __launch_bounds__(256) k_att2(
        const float* __restrict__ b1u, const float* __restrict__ b1i, int n)
{
    extern __shared__ __nv_bfloat16 smh[];
    __nv_bfloat16* As = smh;
    __nv_bfloat16* Bs = smh + 128 * SST;
    __shared__ float sred[DD];
    int t = threadIdx.x;
    int path = blockIdx.x / ATT_BLOCKS;
    int blk = blockIdx.x % ATT_BLOCKS;
    int side = path >> 1;
    const __nv_bfloat16* zh = d_zh + (size_t)path * NU * DD;
    const __nv_bfloat16* w1h = d_w1h + (size_t)side * DD * DD;
    const float* b1 = side ? b1i : b1u;
    float* att = d_att + path * DD;
    int row0 = blk * 128;
    if (t < DD) sred[t] = 0.f;
    for (int i = t; i < 2048; i += 256) {
        int r = i >> 4, c = i & 15;
        uint4 v = make_uint4(0, 0, 0, 0);
        if (row0 + r < n) v = *(const uint4*)(zh + (size_t)(row0 + r) * DD + c * 8);
        *(uint4*)(As + r * SST + c * 8) = v;
        *(uint4*)(Bs + r * SST + c * 8) = *(const uint4*)(w1h + (size_t)r * DD + c * 8);
    }
    __syncthreads();
    int warp = t >> 5, lane = t & 31;
    int wm = warp >> 1, wn = warp & 1;
    float acc[2][8][4] = {};
    uint32_t a_base = smem_u32(As + (wm * 32 + (lane & 15)) * SST + (lane >> 4) * 8);
    uint32_t b_base = smem_u32(Bs + (wn * 64 + (lane >> 4) * 8 + (lane & 7)) * SST +
                               ((lane >> 3) & 1) * 8);
#pragma unroll
    for (int ks = 0; ks < 8; ks++) {
        uint32_t a[2][4], b[4][4];
        ldmx4(a[0], a_base + ks * 32);
        ldmx4(a[1], a_base + 16 * SST * 2 + ks * 32);
#pragma unroll
        for (int p = 0; p < 4; p++)
            ldmx4(b[p], b_base + p * 16 * SST * 2 + ks * 32);
#pragma unroll
        for (int mi = 0; mi < 2; mi++)
#pragma unroll
            for (int nt = 0; nt < 8; nt++)
                mma_bf16(acc[mi][nt], a[mi], &b[nt >> 1][(nt & 1) * 2]);
    }
    float b1v[8][2];
#pragma unroll
    for (int nt = 0; nt < 8; nt++) {
        int col = wn * 64 + nt * 8 + 2 * (lane & 3);
        b1v[nt][0] = __ldg(b1 + col);
        b1v[nt][1] = __ldg(b1 + col + 1);
    }
    float cs[8][2] = {};
    int r_lo = row0 + wm * 32 + (lane >> 2);
#pragma unroll
    for (int mi = 0; mi < 2; mi++) {
        int ra = r_lo + mi * 16, rb = ra + 8;
        bool va = ra < n, vb = rb < n;
#pragma unroll
        for (int nt = 0; nt < 8; nt++) {
            if (va) {
                cs[nt][0] += tanh_ap(acc[mi][nt][0] + b1v[nt][0]);
                cs[nt][1] += tanh_ap(acc[mi][nt][1] + b1v[nt][1]);
            }
            if (vb) {
                cs[nt][0] += tanh_ap(acc[mi][nt][2] + b1v[nt][0]);
                cs[nt][1] += tanh_ap(acc[mi][nt][3] + b1v[nt][1]);
            }
        }
    }
#pragma unroll
    for (int o = 4; o <= 16; o <<= 1)
#pragma unroll
        for (int nt = 0; nt < 8; nt++) {
            cs[nt][0] += __shfl_xor_sync(0xffffffffu, cs[nt][0], o);
            cs[nt][1] += __shfl_xor_sync(0xffffffffu, cs[nt][1], o);
        }
    if (lane < 4) {
#pragma unroll
        for (int nt = 0; nt < 8; nt++) {
            int col = wn * 64 + nt * 8 + 2 * lane;
            atomicAdd(&sred[col], cs[nt][0]);
            atomicAdd(&sred[col + 1], cs[nt][1]);
        }
    }
    __syncthreads();
    if (t < DD) atomicAdd(&att[t], sred[t]);
}

__global__ void k_beta2(const float* __restrict__ W2u, const float* __restrict__ W2i) {
    int side = blockIdx.x;
    const float* W2 = side ? W2i : W2u;
    int lane = threadIdx.x;
    float w0 = 0.f, w1 = 0.f;
    for (int k = lane; k < DD; k += 32) {
        float wv = __ldg(W2 + k);
        w0 += d_att[side * 2 * DD + k] * wv;
        w1 += d_att[side * 2 * DD + DD + k] * wv;
    }
    for (int o = 16; o; o >>= 1) {
        w0 += __shfl_xor_sync(0xffffffffu, w0, o);
        w1 += __shfl_xor_sync(0xffffffffu, w1, o);
    }
    w0 *= (1.f / NU);
    w1 *= (1.f / NU);
    float m = fmaxf(w0, w1);
    float e0 = expf(w0 - m), e1 = expf(w1 - m);
    float den = 1.f / (e0 + e1);
    if (lane == 0) {
        d_beta[side * 2]     = e0 * den;
        d_beta[side * 2 + 1] = e1 * den;
    }
    for (int k = lane; k < 2 * DD; k += 32) d_att[side * 2 * DD + k] = 0.f;
}

__global__ void k_combine(const float* __restrict__ z) {
    int i = blockIdx.x * blockDim.x + threadIdx.x;
    if (i < NU * DD) {
        d_h[i]           = d_beta[0] * z[i] + d_beta[1] * z[i + NU * DD];
        d_h[NU * DD + i] = d_beta[2] * z[2 * NU * DD + i] + d_beta[3] * z[3 * NU * DD + i];
    }
}

__global__ void k_emb(const float* __restrict__ xf) {
    int i = blockIdx.x * blockDim.x + threadIdx.x;
    if (i < NU * DD) {
        d_emb[i]           = 0.5f * (d_h[i] + xf[i]);
        d_emb[NU * DD + i] = 0.5f * (d_h[NU * DD + i] + xf[NU * DD + i]);
    }
}

// ------------------------- SSL ----------------------------------------------
__global__ void __launch_bounds__(256) k_norm(
        const float* __restrict__ e1base, const float* __restrict__ e2base,
        const int* __restrict__ idx0, const int* __restrict__ idx1)
{
    int slot = blockIdx.y;
    const float* e1b = e1base + (size_t)slot * NU * DD;
    const float* e2b = e2base + (size_t)slot * NU * DD;
    const int* idx = slot ? idx1 : idx0;
    int gid = blockIdx.x * blockDim.x + threadIdx.x;
    int r = gid >> 5;
    if (r >= BSZ) return;
    int lane = gid & 31;
    int row = idx[r];
    float4 a = *(const float4*)(e1b + (size_t)row * DD + lane * 4);
    float4 b = *(const float4*)(e2b + (size_t)row * DD + lane * 4);
    float s11 = a.x * a.x + a.y * a.y + a.z * a.z + a.w * a.w;
    float s22 = b.x * b.x + b.y * b.y + b.z * b.z + b.w * b.w;
    float s12 = a.x * b.x + a.y * b.y + a.z * b.z + a.w * b.w;
    for (int o = 16; o; o >>= 1) {
        s11 += __shfl_xor_sync(0xffffffffu, s11, o);
        s22 += __shfl_xor_sync(0xffffffffu, s22, o);
        s12 += __shfl_xor_sync(0xffffffffu, s12, o);
    }
    float i1 = 1.f / fmaxf(sqrtf(s11), 1e-12f);
    float i2 = 1.f / fmaxf(sqrtf(s22), 1e-12f);
    if (lane == 0) {
        d_dpos[slot * BSZ + r] = s12 * i1 * i2;
        d_alls[slot * BSZ + r] = 0.f;
    }
    __nv_bfloat162 na0 = __floats2bfloat162_rn(a.x * i1, a.y * i1);
    __nv_bfloat162 na1 = __floats2bfloat162_rn(a.z * i1, a.w * i1);
    __nv_bfloat162 nb0 = __floats2bfloat162_rn(b.x * i2, b.y * i2);
    __nv_bfloat162 nb1 = __floats2bfloat162_rn(b.z * i2, b.w * i2);
    uint2 wa, wb;
    wa.x = *(uint32_t*)&na0; wa.y = *(uint32_t*)&na1;
    wb.x = *(uint32_t*)&nb0; wb.y = *(uint32_t*)&nb1;
    size_t base = (size_t)slot * BSZ * DD + (size_t)r * DD + lane * 4;
    *(uint2*)(d_n1h + base) = wa;
    *(uint2*)(d_n2h + base) = wb;
}

__global__ void __launch_bounds__(256) k_sslgemm_mma()
{
    extern __shared__ __nv_bfloat16 smh[];
    __nv_bfloat16* As = smh;
    __nv_bfloat16* Bs = smh + 128 * SST;
    __shared__ float sred[128];
    int t = threadIdx.x;
    int slot = blockIdx.z;
    int rowA0 = blockIdx.y * 128, colB0 = blockIdx.x * 128;
    const __nv_bfloat16* n1 = d_n1h + (size_t)slot * BSZ * DD;
    const __nv_bfloat16* n2 = d_n2h + (size_t)slot * BSZ * DD;
    if (t < 128) sred[t] = 0.f;
    for (int i = t; i < 2048; i += 256) {
        int r = i >> 4, c = i & 15;
        *(uint4*)(As + r * SST + c * 8) = *(const uint4*)(n1 + (size_t)(rowA0 + r) * DD + c * 8);
        *(uint4*)(Bs + r * SST + c * 8) = *(const uint4*)(n2 + (size_t)(colB0 + r) * DD + c * 8);
    }
    __syncthreads();
    int warp = t >> 5, lane = t & 31;
    int wm = warp >> 1, wn = warp & 1;
    float acc[2][8][4] = {};
    uint32_t a_base = smem_u32(As + (wm * 32 + (lane & 15)) * SST + (lane >> 4) * 8);
    uint32_t b_base = smem_u32(Bs + (wn * 64 + (lane >> 4) * 8 + (lane & 7)) * SST +
                               ((lane >> 3) & 1) * 8);
#pragma unroll
    for (int ks = 0; ks < 8; ks++) {
        uint32_t a[2][4], b[4][4];
        ldmx4(a[0], a_base + ks * 32);
        ldmx4(a[1], a_base + 16 * SST * 2 + ks * 32);
#pragma unroll
        for (int p = 0; p < 4; p++)
            ldmx4(b[p], b_base + p * 16 * SST * 2 + ks * 32);
#pragma unroll
        for (int mi = 0; mi < 2; mi++)
#pragma unroll
            for (int nt = 0; nt < 8; nt++)
                mma_bf16(acc[mi][nt], a[mi], &b[nt >> 1][(nt & 1) * 2]);
    }
    float rs[2][2] = {};
#pragma unroll
    for (int mi = 0; mi < 2; mi++)
#pragma unroll
        for (int nt = 0; nt < 8; nt++) {
            rs[mi][0] += ex2_ap(acc[mi][nt][0] * TWO_LOG2E) + ex2_ap(acc[mi][nt][1] * TWO_LOG2E);
            rs[mi][1] += ex2_ap(acc[mi][nt][2] * TWO_LOG2E) + ex2_ap(acc[mi][nt][3] * TWO_LOG2E);
        }
#pragma unroll
    for (int o = 1; o <= 2; o <<= 1) {
        rs[0][0] += __shfl_xor_sync(0xffffffffu, rs[0][0], o);
        rs[0][1] += __shfl_xor_sync(0xffffffffu, rs[0][1], o);
        rs[1][0] += __shfl_xor_sync(0xffffffffu, rs[1][0], o);
        rs[1][1] += __shfl_xor_sync(0xffffffffu, rs[1][1], o);
    }
    if ((lane & 3) == 0) {
        int r0 = wm * 32 + (lane >> 2);
        atomicAdd(&sred[r0],      rs[0][0]);
        atomicAdd(&sred[r0 + 8],  rs[0][1]);
        atomicAdd(&sred[r0 + 16], rs[1][0]);
        atomicAdd(&sred[r0 + 24], rs[1][1]);
    }
    __syncthreads();
    if (t < 128) atomicAdd(&d_alls[slot * BSZ + rowA0 + t], sred[t]);
}

__global__ void k_sslreduce(float* dst, float scale) {
    __shared__ float sp[256];
    int t = threadIdx.x;
    float s = 0.f;
    for (int i = t; i < 2 * BSZ; i += 256)
        s += logf(d_alls[i]) - 2.f * d_dpos[i];
    sp[t] = s;
    __syncthreads();
    for (int o = 128; o; o >>= 1) {
        if (t < o) sp[t] += sp[t + o];
        __syncthreads();
    }
    if (t == 0) dst[0] = sp[0] * scale;
}

// ------------- final: out = LN(relu(emb[idx] @ W + b)); 3 jobs via grid.y ---
__global__ void __launch_bounds__(256) k_final(
        const float* __restrict__ emb_u, const float* __restrict__ emb_i,
        const int* __restrict__ idx_u, const int* __restrict__ idx_i,
        const int* __restrict__ idx_n,
        const float* __restrict__ Wu, const float* __restrict__ bu,
        const float* __restrict__ Wi, const float* __restrict__ bi,
        const float* __restrict__ lng, const float* __restrict__ lnb,
        float* __restrict__ outb)
{
    extern __shared__ float smf[];
    float* Ws = smf;
    float* Zs = smf + 16384;
    int which = blockIdx.y;
    const float* embb = (which == 0) ? emb_u : emb_i;
    const int* idx = (which == 0) ? idx_u : ((which == 1) ? idx_i : idx_n);
    const float* W = (which == 0) ? Wu : Wi;
    const float* bias = (which == 0) ? bu : bi;
    float* outp = outb + (size_t)which * BSZ * DD;
    int t = threadIdx.x;
    for (int i = t; i < 4096; i += 256)
        ((float4*)Ws)[i] = ((const float4*)W)[i];
    __syncthreads();
    int warp = t >> 5, lane = t & 31;
    int base = (blockIdx.x * 8 + warp) * 4;
    float* zr = Zs + warp * 512;
    for (int i = lane; i < 128; i += 32) {
        int r = i >> 5, c = i & 31;
        ((float4*)zr)[i] = ((const float4*)(embb + (size_t)idx[base + r] * DD))[c];
    }
    __syncwarp();
    float4 bb = ((const float4*)bias)[lane];
    float acc[4][4];
#pragma unroll
    for (int r = 0; r < 4; r++) {
        acc[r][0] = bb.x; acc[r][1] = bb.y; acc[r][2] = bb.z; acc[r][3] = bb.w;
    }
#pragma unroll 4
    for (int k = 0; k < DD; k++) {
        float4 w = *(const float4*)(Ws + k * DD + lane * 4);
        float zv[4];
        zv[0] = zr[k]; zv[1] = zr[DD + k]; zv[2] = zr[2 * DD + k]; zv[3] = zr[3 * DD + k];
#pragma unroll
        for (int r = 0; r < 4; r++) {
            acc[r][0] = fmaf(zv[r], w.x, acc[r][0]);
            acc[r][1] = fmaf(zv[r], w.y, acc[r][1]);
            acc[r][2] = fmaf(zv[r], w.z, acc[r][2]);
            acc[r][3] = fmaf(zv[r], w.w, acc[r][3]);
        }
    }
    float4 g4 = ((const float4*)lng)[lane];
    float4 lb4 = ((const float4*)lnb)[lane];
#pragma unroll
    for (int r = 0; r < 4; r++) {
        float v0 = fmaxf(acc[r][0], 0.f), v1 = fmaxf(acc[r][1], 0.f);
        float v2 = fmaxf(acc[r][2], 0.f), v3 = fmaxf(acc[r][3], 0.f);
        float s = v0 + v1 + v2 + v3;
        for (int o = 16; o; o >>= 1) s += __shfl_xor_sync(0xffffffffu, s, o);
        float mu = s * (1.f / 128.f);
        float w0 = v0 - mu, w1 = v1 - mu, w2 = v2 - mu, w3 = v3 - mu;
        float q = w0 * w0 + w1 * w1 + w2 * w2 + w3 * w3;
        for (int o = 16; o; o >>= 1) q += __shfl_xor_sync(0xffffffffu, q, o);
        float inv = rsqrtf(q * (1.f / 128.f) + 1e-5f);
        float4 ov;
        ov.x = w0 * inv * g4.x + lb4.x;
        ov.y = w1 * inv * g4.y + lb4.y;
        ov.z = w2 * inv * g4.z + lb4.z;
        ov.w = w3 * inv * g4.w + lb4.w;
        *(float4*)(outp + (size_t)(base + r) * DD + lane * 4) = ov;
    }
}

// ------------------------- host orchestration -------------------------------
extern "C" void kernel_launch(void* const* d_in, const int* in_sizes, int n_in,
                              void* d_out, int out_size)
{
    const float* feat_user = (const float*)d_in[0];
    const float* feat_item = (const float*)d_in[1];
    const float* u_W1 = (const float*)d_in[2];
    const float* u_b1 = (const float*)d_in[3];
    const float* u_W2 = (const float*)d_in[4];
    const float* i_W1 = (const float*)d_in[5];
    const float* i_b1 = (const float*)d_in[6];
    const float* i_W2 = (const float*)d_in[7];
    const float* user_W = (const float*)d_in[8];
    const float* user_b = (const float*)d_in[9];
    const float* item_W = (const float*)d_in[10];
    const float* item_b = (const float*)d_in[11];
    const float* ln_g = (const float*)d_in[12];
    const float* ln_b = (const float*)d_in[13];
    const int* mpsrc[4] = {(const int*)d_in[14], (const int*)d_in[16],
                           (const int*)d_in[18], (const int*)d_in[20]};
    const int* mpdst[4] = {(const int*)d_in[15], (const int*)d_in[17],
                           (const int*)d_in[19], (const int*)d_in[21]};
    const int* ui_row = (const int*)d_in[22];
    const int* ui_col = (const int*)d_in[23];
    const int* user_idx = (const int*)d_in[24];
    const int* item_idx = (const int*)d_in[25];
    const int* neg_idx = (const int*)d_in[26];
    float* out = (float*)d_out;

    float *p_h, *p_z, *p_x, *p_emb, *p_rout, *p_rin, *p_dinv;
    int *p_deg, *p_off, *p_cur, *p_csr, *p_cntui, *p_offui, *p_curui, *p_csrui;
    __nv_bfloat16 *p_zh, *p_w1h;
    cudaGetSymbolAddress((void**)&p_h, d_h);
    cudaGetSymbolAddress((void**)&p_z, d_z);
    cudaGetSymbolAddress((void**)&p_zh, d_zh);
    cudaGetSymbolAddress((void**)&p_w1h, d_w1h);
    cudaGetSymbolAddress((void**)&p_x, d_x);
    cudaGetSymbolAddress((void**)&p_emb, d_emb);
    cudaGetSymbolAddress((void**)&p_rout, d_rout);
    cudaGetSymbolAddress((void**)&p_rin, d_rin);
    cudaGetSymbolAddress((void**)&p_dinv, d_dinv);
    cudaGetSymbolAddress((void**)&p_deg, d_deg);
    cudaGetSymbolAddress((void**)&p_off, d_off);
    cudaGetSymbolAddress((void**)&p_cur, d_cur);
    cudaGetSymbolAddress((void**)&p_csr, d_csr);
    cudaGetSymbolAddress((void**)&p_cntui, d_cntui);
    cudaGetSymbolAddress((void**)&p_offui, d_offui);
    cudaGetSymbolAddress((void**)&p_curui, d_curui);
    cudaGetSymbolAddress((void**)&p_csrui, d_csrui);

    const int T = 256;
    const int GEMM_SMEM = 2 * 128 * SST * 2;
    cudaFuncSetAttribute(k_att2, cudaFuncAttributeMaxDynamicSharedMemorySize, GEMM_SMEM);
    cudaFuncSetAttribute(k_sslgemm_mma, cudaFuncAttributeMaxDynamicSharedMemorySize, GEMM_SMEM);
    cudaFuncSetAttribute(k_final, cudaFuncAttributeMaxDynamicSharedMemorySize, 81920);

    // ---- CSR build ----
    k_zero2<<<(8 * NU + NTOT + T - 1) / T, T>>>(p_deg, 8 * NU, p_cntui, NTOT);
    k_count_all<<<(8 * (EMP / 4) + EUI / 4 + T - 1) / T, T>>>(
        mpsrc[0], mpdst[0], mpsrc[1], mpdst[1],
        mpsrc[2], mpdst[2], mpsrc[3], mpdst[3], ui_row, p_deg, p_cntui);
    k_prep<<<(4 * NU + T - 1) / T, T>>>(p_deg, p_rout, p_rin, p_cntui, p_dinv);
    k_scan5<<<5, 1024>>>();
    {
        dim3 gf((EMP + T - 1) / T, 4);
        k_fill_mp<<<gf, T>>>(mpdst[0], mpsrc[0], mpdst[1], mpsrc[1],
                             mpdst[2], mpsrc[2], mpdst[3], mpsrc[3], p_cur, p_csr);
    }
    k_fill<<<(EUI + T - 1) / T, T>>>(ui_row, ui_col, EUI, p_curui, p_csrui);

    // ---- HAN: both sides fused ----
    k_cvtW2<<<(2 * DD * DD + T - 1) / T, T>>>(u_W1, i_W1, p_w1h);
    {
        dim3 gp((NU * 32) / T, 4);
        for (int layer = 0; layer < 3; layer++) {
            const float* h0 = layer ? p_h : feat_user;
            const float* h1 = layer ? p_h + (size_t)NU * DD : feat_item;
            k_pull<<<gp, T>>>(h0, h1, NU, p_rout, p_rin, p_off, p_csr,
                              p_z, p_zh, NU, NU, NU + 1, EMP, NU * DD);
            k_att2<<<4 * ATT_BLOCKS, 256, GEMM_SMEM>>>(u_b1, i_b1, NU);
            k_beta2<<<2, 32>>>(u_W2, i_W2);
            k_combine<<<(NU * DD + T - 1) / T, T>>>(p_z);
        }
    }

    // ---- LightGCN (3 hops, no copies) ----
    float* x0 = p_x;
    float* x1 = p_x + (size_t)NTOT * DD;
    dim3 gu((NTOT * 32) / T, 1);
    k_pull<<<gu, T>>>(feat_user, feat_item, NU, p_dinv, p_dinv, p_offui, p_csrui,
                      x1, (__nv_bfloat16*)0, NTOT, 0, 0, 0, 0);
    k_pull<<<gu, T>>>(x1, x1 + (size_t)NU * DD, NU, p_dinv, p_dinv, p_offui, p_csrui,
                      x0, (__nv_bfloat16*)0, NTOT, 0, 0, 0, 0);
    k_pull<<<gu, T>>>(x0, x0 + (size_t)NU * DD, NU, p_dinv, p_dinv, p_offui, p_csrui,
                      x1, (__nv_bfloat16*)0, NTOT, 0, 0, 0, 0);
    float* xf = x1;

    // ---- combine embeddings ----
    k_emb<<<(NU * DD + T - 1) / T, T>>>(xf);

    // ---- SSL ----
    {
        dim3 gn((BSZ * 32) / T, 2);
        k_norm<<<gn, T>>>(xf, p_emb, user_idx, item_idx);
    }
    {
        dim3 gg(BSZ / 128, BSZ / 128, 2);
        k_sslgemm_mma<<<gg, 256, GEMM_SMEM>>>();
    }
    k_sslreduce<<<1, 256>>>(out + (size_t)3 * BSZ * DD, 0.4f / (float)BSZ);

    // ---- final (one launch, 3 jobs) ----
    {
        dim3 gfin(BSZ / 32, 3);
        k_final<<<gfin, 256, 81920>>>(p_emb, p_emb + (size_t)NU * DD,
                                      user_idx, item_idx, neg_idx,
                                      user_W, user_b, item_W, item_b,
                                      ln_g, ln_b, out);
    }
}

// round 17
// speedup vs baseline: 1.4296x; 1.1375x over previous
#include <cuda_runtime.h>
#include <cuda_bf16.h>
#include <stdint.h>
#include <math.h>

#define DD   128
#define NU   40000
#define NTOT 80000
#define EMP  640000
#define EUI  1600000
#define BSZ  8192
#define ATT_BLOCKS 313
#define SST 136
#define TILE 2048
#define NU_TILES 20      // ceil(40000/2048)
#define UI_TILES 40      // ceil(80000/2048)
#define TOT_TILES (4 * NU_TILES + UI_TILES)

// ------------------------- static device scratch ----------------------------
__device__ float d_h[2 * NU * DD];
__device__ float d_z[4 * NU * DD];
__device__ __nv_bfloat16 d_zh[4 * NU * DD];
__device__ __nv_bfloat16 d_w1h[2 * DD * DD];
__device__ float d_x[2 * NTOT * DD];
__device__ float d_rout[4 * NU];
__device__ float d_rin[4 * NU];
__device__ int   d_deg[8 * NU];
__device__ int   d_off[4 * (NU + 1)];
__device__ int   d_cur[4 * NU];
__device__ int   d_csr[4 * EMP];
__device__ int   d_cntui[NTOT];
__device__ float d_dinv[NTOT];
__device__ int   d_offui[NTOT + 1];
__device__ int   d_curui[NTOT];
__device__ int   d_csrui[EUI];
__device__ float d_att[4 * DD];
__device__ float d_beta[4];
__device__ __nv_bfloat16 d_n1h[2 * BSZ * DD];
__device__ __nv_bfloat16 d_n2h[2 * BSZ * DD];
__device__ float d_alls[2 * BSZ];
__device__ float d_dpos[2 * BSZ];
__device__ int   d_tilesum[TOT_TILES];
__device__ int   d_tilepre[TOT_TILES];

// ------------------------- math / mma helpers -------------------------------
__device__ __forceinline__ uint32_t smem_u32(const void* p) {
    return (uint32_t)__cvta_generic_to_shared(const_cast<void*>(p));
}
__device__ __forceinline__ void ldmx4(uint32_t* r, uint32_t a) {
    asm volatile("ldmatrix.sync.aligned.m8n8.x4.shared.b16 {%0,%1,%2,%3}, [%4];"
        : "=r"(r[0]), "=r"(r[1]), "=r"(r[2]), "=r"(r[3]) : "r"(a));
}
__device__ __forceinline__ void mma_bf16(float* c, const uint32_t* a, const uint32_t* b) {
    asm volatile(
        "mma.sync.aligned.m16n8k16.row.col.f32.bf16.bf16.f32 "
        "{%0,%1,%2,%3},{%4,%5,%6,%7},{%8,%9},{%0,%1,%2,%3};"
        : "+f"(c[0]), "+f"(c[1]), "+f"(c[2]), "+f"(c[3])
        : "r"(a[0]), "r"(a[1]), "r"(a[2]), "r"(a[3]), "r"(b[0]), "r"(b[1]));
}
__device__ __forceinline__ float tanh_ap(float x) {
    float r;
    asm("tanh.approx.f32 %0, %1;" : "=f"(r) : "f"(x));
    return r;
}
__device__ __forceinline__ float ex2_ap(float x) {
    float r;
    asm("ex2.approx.f32 %0, %1;" : "=f"(r) : "f"(x));
    return r;
}
#define TWO_LOG2E 2.885390081777927f

// ------------------------- CSR build -----------------------------------------
__global__ void k_zero2(int* a, int na, int* b, int nb) {
    int i = blockIdx.x * blockDim.x + threadIdx.x;
    if (i < na) a[i] = 0;
    else if (i < na + nb) b[i - na] = 0;
}
__global__ void k_count_all(const int* s0, const int* d0, const int* s1, const int* d1,
                            const int* s2, const int* d2, const int* s3, const int* d3,
                            const int* uir, int* deg, int* cntui) {
    const int Q = EMP / 4;
    int t = blockIdx.x * blockDim.x + threadIdx.x;
    if (t < 8 * Q) {
        int seg = t / Q;
        int o = (t - seg * Q) * 4;
        const int* arr;
        int* cnt;
        switch (seg) {
            case 0: arr = s0; cnt = deg + 0 * NU; break;
            case 1: arr = d0; cnt = deg + 4 * NU; break;
            case 2: arr = s1; cnt = deg + 1 * NU; break;
            case 3: arr = d1; cnt = deg + 5 * NU; break;
            case 4: arr = s2; cnt = deg + 2 * NU; break;
            case 5: arr = d2; cnt = deg + 6 * NU; break;
            case 6: arr = s3; cnt = deg + 3 * NU; break;
            default: arr = d3; cnt = deg + 7 * NU; break;
        }
        int4 v = *(const int4*)(arr + o);
        atomicAdd(&cnt[v.x], 1);
        atomicAdd(&cnt[v.y], 1);
        atomicAdd(&cnt[v.z], 1);
        atomicAdd(&cnt[v.w], 1);
    } else {
        int u = t - 8 * Q;
        if (u < EUI / 4) {
            int4 v = *(const int4*)(uir + u * 4);
            atomicAdd(&cntui[v.x], 1);
            atomicAdd(&cntui[v.y], 1);
            atomicAdd(&cntui[v.z], 1);
            atomicAdd(&cntui[v.w], 1);
        }
    }
}
__global__ void k_prep(const int* __restrict__ deg, float* __restrict__ rout,
                       float* __restrict__ rin, const int* __restrict__ cntui,
                       float* __restrict__ dinv) {
    int i = blockIdx.x * blockDim.x + threadIdx.x;
    if (i < 4 * NU) {
        rout[i] = rsqrtf(fmaxf((float)deg[i], 1.f));
        rin[i]  = rsqrtf(fmaxf((float)deg[4 * NU + i], 1.f));
    }
    if (i < NTOT) {
        int c = cntui[i];
        dinv[i] = (c > 0) ? rsqrtf((float)c) : 0.f;
    }
}
// ---- hierarchical segmented scan: A (tile scan) / B (tile-sum scan) / C (add)
__device__ __forceinline__ void scan_seg(int g, int& seg, int& ti) {
    if (g < 4 * NU_TILES) { seg = g / NU_TILES; ti = g % NU_TILES; }
    else                  { seg = 4; ti = g - 4 * NU_TILES; }
}
__global__ void __launch_bounds__(256) k_scanA() {
    int g = blockIdx.x, seg, ti;
    scan_seg(g, seg, ti);
    const int* cnt;
    int* off;
    int n;
    if (seg < 4) { cnt = d_deg + (4 + seg) * NU; off = d_off + seg * (NU + 1); n = NU; }
    else         { cnt = d_cntui; off = d_offui; n = NTOT; }
    int t = threadIdx.x;
    int idx0 = ti * TILE + t * 8;
    int v[8];
    int s = 0;
#pragma unroll
    for (int i = 0; i < 8; i++) {
        int gi = idx0 + i;
        v[i] = (gi < n) ? cnt[gi] : 0;
        s += v[i];
    }
    int lane = t & 31, w = t >> 5;
    int ps = s;
#pragma unroll
    for (int o = 1; o < 32; o <<= 1) {
        int u = __shfl_up_sync(0xffffffffu, ps, o);
        if (lane >= o) ps += u;
    }
    __shared__ int wsum[8];
    __shared__ int wpre[8];
    if (lane == 31) wsum[w] = ps;
    __syncthreads();
    if (t == 0) {
        int r = 0;
#pragma unroll
        for (int i = 0; i < 8; i++) { wpre[i] = r; r += wsum[i]; }
    }
    __syncthreads();
    int run = wpre[w] + ps - s;
#pragma unroll
    for (int i = 0; i < 8; i++) {
        int gi = idx0 + i;
        if (gi < n) off[gi] = run;
        run += v[i];
    }
    if (t == 255) d_tilesum[g] = wpre[7] + ps;
}
__global__ void k_scanB() {
    int t = threadIdx.x;
    if (t < 5) {
        int start = (t < 4) ? t * NU_TILES : 4 * NU_TILES;
        int cnt = (t < 4) ? NU_TILES : UI_TILES;
        int r = 0;
        for (int i = 0; i < cnt; i++) {
            d_tilepre[start + i] = r;
            r += d_tilesum[start + i];
        }
        if (t < 4) d_off[t * (NU + 1) + NU] = r;
        else       d_offui[NTOT] = r;
    }
}
__global__ void __launch_bounds__(256) k_scanC() {
    int g = blockIdx.x, seg, ti;
    scan_seg(g, seg, ti);
    int* off;
    int* cur;
    int n;
    if (seg < 4) { off = d_off + seg * (NU + 1); cur = d_cur + seg * NU; n = NU; }
    else         { off = d_offui; cur = d_curui; n = NTOT; }
    int p = d_tilepre[g];
    int idx0 = ti * TILE + threadIdx.x * 8;
#pragma unroll
    for (int i = 0; i < 8; i++) {
        int gi = idx0 + i;
        if (gi < n) {
            int vv = off[gi] + p;
            off[gi] = vv;
            cur[gi] = vv;
        }
    }
}
__global__ void k_fill_mp(const int* k0, const int* v0, const int* k1, const int* v1,
                          const int* k2, const int* v2, const int* k3, const int* v3,
                          int* cur, int* csr) {
    int path = blockIdx.y;
    int i = blockIdx.x * blockDim.x + threadIdx.x;
    if (i >= EMP) return;
    const int* key;
    const int* val;
    switch (path) {
        case 0: key = k0; val = v0; break;
        case 1: key = k1; val = v1; break;
        case 2: key = k2; val = v2; break;
        default: key = k3; val = v3; break;
    }
    int slot = atomicAdd(&cur[path * NU + key[i]], 1);
    csr[(size_t)path * EMP + slot] = val[i];
}
__global__ void k_fill(const int* __restrict__ key, const int* __restrict__ val,
                       int n, int* __restrict__ cur, int* __restrict__ csr) {
    int i = blockIdx.x * blockDim.x + threadIdx.x;
    if (i < n) {
        int slot = atomicAdd(&cur[key[i]], 1);
        csr[slot] = val[i];
    }
}
__global__ void k_cvtW2(const float* __restrict__ Wu, const float* __restrict__ Wi,
                        __nv_bfloat16* __restrict__ Wh) {
    int i = blockIdx.x * blockDim.x + threadIdx.x;
    if (i < 4 * DD) d_att[i] = 0.f;
    if (i < 2 * DD * DD) {
        int side = i >> 14;
        int r = i & 16383;
        int k = r >> 7, nn = r & 127;
        const float* W = side ? Wi : Wu;
        Wh[side * DD * DD + nn * DD + k] = __float2bfloat16(W[r]);
    }
}

// ------------------------- pull-style graph conv ----------------------------
__global__ void __launch_bounds__(256) k_pull(
        const float* __restrict__ h0, const float* __restrict__ h1, int split,
        const float* __restrict__ rout, const float* __restrict__ rin,
        const int* __restrict__ off, const int* __restrict__ csr,
        float* __restrict__ z, __nv_bfloat16* __restrict__ zh, int n,
        int nodeStride, int offStride, int edgeStride, int featStride)
{
    int path = blockIdx.y;
    rout += (size_t)path * nodeStride;
    rin  += (size_t)path * nodeStride;
    off  += (size_t)path * offStride;
    csr  += (size_t)path * edgeStride;
    z    += (size_t)path * featStride;
    if (zh) zh += (size_t)path * featStride;
    int ofs = (path >> 1) * split;

    int gid = blockIdx.x * blockDim.x + threadIdx.x;
    int v = gid >> 5;
    if (v >= n) return;
    int col = (gid & 31) << 2;
    int j = off[v], jend = off[v + 1];
    float ax = 0.f, ay = 0.f, az = 0.f, aw = 0.f;
    for (; j + 4 <= jend; j += 4) {
        int s0 = csr[j], s1 = csr[j + 1], s2 = csr[j + 2], s3 = csr[j + 3];
        float r0 = __ldg(rout + s0), r1 = __ldg(rout + s1);
        float r2 = __ldg(rout + s2), r3 = __ldg(rout + s3);
        int e0 = s0 + ofs, e1 = s1 + ofs, e2 = s2 + ofs, e3 = s3 + ofs;
        const float* p0 = (e0 < split) ? h0 + (size_t)e0 * DD : h1 + (size_t)(e0 - split) * DD;
        const float* p1 = (e1 < split) ? h0 + (size_t)e1 * DD : h1 + (size_t)(e1 - split) * DD;
        const float* p2 = (e2 < split) ? h0 + (size_t)e2 * DD : h1 + (size_t)(e2 - split) * DD;
        const float* p3 = (e3 < split) ? h0 + (size_t)e3 * DD : h1 + (size_t)(e3 - split) * DD;
        float4 h0v = *(const float4*)(p0 + col);
        float4 h1v = *(const float4*)(p1 + col);
        float4 h2v = *(const float4*)(p2 + col);
        float4 h3v = *(const float4*)(p3 + col);
        ax += h0v.x * r0 + h1v.x * r1 + h2v.x * r2 + h3v.x * r3;
        ay += h0v.y * r0 + h1v.y * r1 + h2v.y * r2 + h3v.y * r3;
        az += h0v.z * r0 + h1v.z * r1 + h2v.z * r2 + h3v.z * r3;
        aw += h0v.w * r0 + h1v.w * r1 + h2v.w * r2 + h3v.w * r3;
    }
    for (; j < jend; j++) {
        int s = csr[j];
        float r = __ldg(rout + s);
        int e = s + ofs;
        const float* p = (e < split) ? h0 + (size_t)e * DD : h1 + (size_t)(e - split) * DD;
        float4 hv = *(const float4*)(p + col);
        ax = fmaf(hv.x, r, ax); ay = fmaf(hv.y, r, ay);
        az = fmaf(hv.z, r, az); aw = fmaf(hv.w, r, aw);
    }
    float ri = rin[v];
    float4 o;
    o.x = ax * ri; o.y = ay * ri; o.z = az * ri; o.w = aw * ri;
    *(float4*)(z + (size_t)v * DD + col) = o;
    if (zh) {
        __nv_bfloat162 q0 = __floats2bfloat162_rn(o.x, o.y);
        __nv_bfloat162 q1 = __floats2bfloat162_rn(o.z, o.w);
        uint2 w;
        w.x = *(uint32_t*)&q0;
        w.y = *(uint32_t*)&q1;
        *(uint2*)(zh + (size_t)v * DD + col) = w;
    }
}

// ------------- semantic attention via tensor cores (4 paths) ----------------
__global__ void __launch_bounds__(256) k_att2(
        const float* __restrict__ b1u, const float* __restrict__ b1i, int n)
{
    extern __shared__ __nv_bfloat16 smh[];
    __nv_bfloat16* As = smh;
    __nv_bfloat16* Bs = smh + 128 * SST;
    __shared__ float sred[DD];
    int t = threadIdx.x;
    int path = blockIdx.x / ATT_BLOCKS;
    int blk = blockIdx.x % ATT_BLOCKS;
    int side = path >> 1;
    const __nv_bfloat16* zh = d_zh + (size_t)path * NU * DD;
    const __nv_bfloat16* w1h = d_w1h + (size_t)side * DD * DD;
    const float* b1 = side ? b1i : b1u;
    float* att = d_att + path * DD;
    int row0 = blk * 128;
    if (t < DD) sred[t] = 0.f;
    for (int i = t; i < 2048; i += 256) {
        int r = i >> 4, c = i & 15;
        uint4 v = make_uint4(0, 0, 0, 0);
        if (row0 + r < n) v = *(const uint4*)(zh + (size_t)(row0 + r) * DD + c * 8);
        *(uint4*)(As + r * SST + c * 8) = v;
        *(uint4*)(Bs + r * SST + c * 8) = *(const uint4*)(w1h + (size_t)r * DD + c * 8);
    }
    __syncthreads();
    int warp = t >> 5, lane = t & 31;
    int wm = warp >> 1, wn = warp & 1;
    float acc[2][8][4] = {};
    uint32_t a_base = smem_u32(As + (wm * 32 + (lane & 15)) * SST + (lane >> 4) * 8);
    uint32_t b_base = smem_u32(Bs + (wn * 64 + (lane >> 4) * 8 + (lane & 7)) * SST +
                               ((lane >> 3) & 1) * 8);
#pragma unroll
    for (int ks = 0; ks < 8; ks++) {
        uint32_t a[2][4], b[4][4];
        ldmx4(a[0], a_base + ks * 32);
        ldmx4(a[1], a_base + 16 * SST * 2 + ks * 32);
#pragma unroll
        for (int p = 0; p < 4; p++)
            ldmx4(b[p], b_base + p * 16 * SST * 2 + ks * 32);
#pragma unroll
        for (int mi = 0; mi < 2; mi++)
#pragma unroll
            for (int nt = 0; nt < 8; nt++)
                mma_bf16(acc[mi][nt], a[mi], &b[nt >> 1][(nt & 1) * 2]);
    }
    float b1v[8][2];
#pragma unroll
    for (int nt = 0; nt < 8; nt++) {
        int col = wn * 64 + nt * 8 + 2 * (lane & 3);
        b1v[nt][0] = __ldg(b1 + col);
        b1v[nt][1] = __ldg(b1 + col + 1);
    }
    float cs[8][2] = {};
    int r_lo = row0 + wm * 32 + (lane >> 2);
#pragma unroll
    for (int mi = 0; mi < 2; mi++) {
        int ra = r_lo + mi * 16, rb = ra + 8;
        bool va = ra < n, vb = rb < n;
#pragma unroll
        for (int nt = 0; nt < 8; nt++) {
            if (va) {
                cs[nt][0] += tanh_ap(acc[mi][nt][0] + b1v[nt][0]);
                cs[nt][1] += tanh_ap(acc[mi][nt][1] + b1v[nt][1]);
            }
            if (vb) {
                cs[nt][0] += tanh_ap(acc[mi][nt][2] + b1v[nt][0]);
                cs[nt][1] += tanh_ap(acc[mi][nt][3] + b1v[nt][1]);
            }
        }
    }
#pragma unroll
    for (int o = 4; o <= 16; o <<= 1)
#pragma unroll
        for (int nt = 0; nt < 8; nt++) {
            cs[nt][0] += __shfl_xor_sync(0xffffffffu, cs[nt][0], o);
            cs[nt][1] += __shfl_xor_sync(0xffffffffu, cs[nt][1], o);
        }
    if (lane < 4) {
#pragma unroll
        for (int nt = 0; nt < 8; nt++) {
            int col = wn * 64 + nt * 8 + 2 * lane;
            atomicAdd(&sred[col], cs[nt][0]);
            atomicAdd(&sred[col + 1], cs[nt][1]);
        }
    }
    __syncthreads();
    if (t < DD) atomicAdd(&att[t], sred[t]);
}

__global__ void k_beta2(const float* __restrict__ W2u, const float* __restrict__ W2i) {
    int side = blockIdx.x;
    const float* W2 = side ? W2i : W2u;
    int lane = threadIdx.x;
    float w0 = 0.f, w1 = 0.f;
    for (int k = lane; k < DD; k += 32) {
        float wv = __ldg(W2 + k);
        w0 += d_att[side * 2 * DD + k] * wv;
        w1 += d_att[side * 2 * DD + DD + k] * wv;
    }
    for (int o = 16; o; o >>= 1) {
        w0 += __shfl_xor_sync(0xffffffffu, w0, o);
        w1 += __shfl_xor_sync(0xffffffffu, w1, o);
    }
    w0 *= (1.f / NU);
    w1 *= (1.f / NU);
    float m = fmaxf(w0, w1);
    float e0 = expf(w0 - m), e1 = expf(w1 - m);
    float den = 1.f / (e0 + e1);
    if (lane == 0) {
        d_beta[side * 2]     = e0 * den;
        d_beta[side * 2 + 1] = e1 * den;
    }
    for (int k = lane; k < 2 * DD; k += 32) d_att[side * 2 * DD + k] = 0.f;
}

__global__ void k_combine(const float* __restrict__ z) {
    int i = blockIdx.x * blockDim.x + threadIdx.x;
    if (i < NU * DD) {
        d_h[i]           = d_beta[0] * z[i] + d_beta[1] * z[i + NU * DD];
        d_h[NU * DD + i] = d_beta[2] * z[2 * NU * DD + i] + d_beta[3] * z[3 * NU * DD + i];
    }
}

// ------------------------- SSL ----------------------------------------------
// e1 = xf[row], e2 = 0.5*(h[row]+xf[row]) computed on the fly (no k_emb pass)
__global__ void __launch_bounds__(256) k_norm(
        const float* __restrict__ xf,
        const int* __restrict__ idx0, const int* __restrict__ idx1)
{
    int slot = blockIdx.y;
    const float* xb = xf + (size_t)slot * NU * DD;
    const float* hb = d_h + (size_t)slot * NU * DD;
    const int* idx = slot ? idx1 : idx0;
    int gid = blockIdx.x * blockDim.x + threadIdx.x;
    int r = gid >> 5;
    if (r >= BSZ) return;
    int lane = gid & 31;
    int row = idx[r];
    float4 a = *(const float4*)(xb + (size_t)row * DD + lane * 4);
    float4 hh = *(const float4*)(hb + (size_t)row * DD + lane * 4);
    float4 b;
    b.x = 0.5f * (a.x + hh.x);
    b.y = 0.5f * (a.y + hh.y);
    b.z = 0.5f * (a.z + hh.z);
    b.w = 0.5f * (a.w + hh.w);
    float s11 = a.x * a.x + a.y * a.y + a.z * a.z + a.w * a.w;
    float s22 = b.x * b.x + b.y * b.y + b.z * b.z + b.w * b.w;
    float s12 = a.x * b.x + a.y * b.y + a.z * b.z + a.w * b.w;
    for (int o = 16; o; o >>= 1) {
        s11 += __shfl_xor_sync(0xffffffffu, s11, o);
        s22 += __shfl_xor_sync(0xffffffffu, s22, o);
        s12 += __shfl_xor_sync(0xffffffffu, s12, o);
    }
    float i1 = 1.f / fmaxf(sqrtf(s11), 1e-12f);
    float i2 = 1.f / fmaxf(sqrtf(s22), 1e-12f);
    if (lane == 0) {
        d_dpos[slot * BSZ + r] = s12 * i1 * i2;
        d_alls[slot * BSZ + r] = 0.f;
    }
    __nv_bfloat162 na0 = __floats2bfloat162_rn(a.x * i1, a.y * i1);
    __nv_bfloat162 na1 = __floats2bfloat162_rn(a.z * i1, a.w * i1);
    __nv_bfloat162 nb0 = __floats2bfloat162_rn(b.x * i2, b.y * i2);
    __nv_bfloat162 nb1 = __floats2bfloat162_rn(b.z * i2, b.w * i2);
    uint2 wa, wb;
    wa.x = *(uint32_t*)&na0; wa.y = *(uint32_t*)&na1;
    wb.x = *(uint32_t*)&nb0; wb.y = *(uint32_t*)&nb1;
    size_t base = (size_t)slot * BSZ * DD + (size_t)r * DD + lane * 4;
    *(uint2*)(d_n1h + base) = wa;
    *(uint2*)(d_n2h + base) = wb;
}

__global__ void __launch_bounds__(256) k_sslgemm_mma()
{
    extern __shared__ __nv_bfloat16 smh[];
    __nv_bfloat16* As = smh;
    __nv_bfloat16* Bs = smh + 128 * SST;
    __shared__ float sred[128];
    int t = threadIdx.x;
    int slot = blockIdx.z;
    int rowA0 = blockIdx.y * 128, colB0 = blockIdx.x * 128;
    const __nv_bfloat16* n1 = d_n1h + (size_t)slot * BSZ * DD;
    const __nv_bfloat16* n2 = d_n2h + (size_t)slot * BSZ * DD;
    if (t < 128) sred[t] = 0.f;
    for (int i = t; i < 2048; i += 256) {
        int r = i >> 4, c = i & 15;
        *(uint4*)(As + r * SST + c * 8) = *(const uint4*)(n1 + (size_t)(rowA0 + r) * DD + c * 8);
        *(uint4*)(Bs + r * SST + c * 8) = *(const uint4*)(n2 + (size_t)(colB0 + r) * DD + c * 8);
    }
    __syncthreads();
    int warp = t >> 5, lane = t & 31;
    int wm = warp >> 1, wn = warp & 1;
    float acc[2][8][4] = {};
    uint32_t a_base = smem_u32(As + (wm * 32 + (lane & 15)) * SST + (lane >> 4) * 8);
    uint32_t b_base = smem_u32(Bs + (wn * 64 + (lane >> 4) * 8 + (lane & 7)) * SST +
                               ((lane >> 3) & 1) * 8);
#pragma unroll
    for (int ks = 0; ks < 8; ks++) {
        uint32_t a[2][4], b[4][4];
        ldmx4(a[0], a_base + ks * 32);
        ldmx4(a[1], a_base + 16 * SST * 2 + ks * 32);
#pragma unroll
        for (int p = 0; p < 4; p++)
            ldmx4(b[p], b_base + p * 16 * SST * 2 + ks * 32);
#pragma unroll
        for (int mi = 0; mi < 2; mi++)
#pragma unroll
            for (int nt = 0; nt < 8; nt++)
                mma_bf16(acc[mi][nt], a[mi], &b[nt >> 1][(nt & 1) * 2]);
    }
    float rs[2][2] = {};
#pragma unroll
    for (int mi = 0; mi < 2; mi++)
#pragma unroll
        for (int nt = 0; nt < 8; nt++) {
            rs[mi][0] += ex2_ap(acc[mi][nt][0] * TWO_LOG2E) + ex2_ap(acc[mi][nt][1] * TWO_LOG2E);
            rs[mi][1] += ex2_ap(acc[mi][nt][2] * TWO_LOG2E) + ex2_ap(acc[mi][nt][3] * TWO_LOG2E);
        }
#pragma unroll
    for (int o = 1; o <= 2; o <<= 1) {
        rs[0][0] += __shfl_xor_sync(0xffffffffu, rs[0][0], o);
        rs[0][1] += __shfl_xor_sync(0xffffffffu, rs[0][1], o);
        rs[1][0] += __shfl_xor_sync(0xffffffffu, rs[1][0], o);
        rs[1][1] += __shfl_xor_sync(0xffffffffu, rs[1][1], o);
    }
    if ((lane & 3) == 0) {
        int r0 = wm * 32 + (lane >> 2);
        atomicAdd(&sred[r0],      rs[0][0]);
        atomicAdd(&sred[r0 + 8],  rs[0][1]);
        atomicAdd(&sred[r0 + 16], rs[1][0]);
        atomicAdd(&sred[r0 + 24], rs[1][1]);
    }
    __syncthreads();
    if (t < 128) atomicAdd(&d_alls[slot * BSZ + rowA0 + t], sred[t]);
}

__global__ void k_sslreduce(float* dst, float scale) {
    __shared__ float sp[256];
    int t = threadIdx.x;
    float s = 0.f;
    for (int i = t; i < 2 * BSZ; i += 256)
        s += logf(d_alls[i]) - 2.f * d_dpos[i];
    sp[t] = s;
    __syncthreads();
    for (int o = 128; o; o >>= 1) {
        if (t < o) sp[t] += sp[t + o];
        __syncthreads();
    }
    if (t == 0) dst[0] = sp[0] * scale;
}

// ------------- final: out = LN(relu(0.5*(h+xf)[idx] @ W + b)) ---------------
__global__ void __launch_bounds__(256) k_final(
        const float* __restrict__ xf,
        const int* __restrict__ idx_u, const int* __restrict__ idx_i,
        const int* __restrict__ idx_n,
        const float* __restrict__ Wu, const float* __restrict__ bu,
        const float* __restrict__ Wi, const float* __restrict__ bi,
        const float* __restrict__ lng, const float* __restrict__ lnb,
        float* __restrict__ outb)
{
    extern __shared__ float smf[];
    float* Ws = smf;
    float* Zs = smf + 16384;
    int which = blockIdx.y;
    size_t ofs = (which == 0) ? 0 : (size_t)NU * DD;
    const float* hb = d_h + ofs;
    const float* xb = xf + ofs;
    const int* idx = (which == 0) ? idx_u : ((which == 1) ? idx_i : idx_n);
    const float* W = (which == 0) ? Wu : Wi;
    const float* bias = (which == 0) ? bu : bi;
    float* outp = outb + (size_t)which * BSZ * DD;
    int t = threadIdx.x;
    for (int i = t; i < 4096; i += 256)
        ((float4*)Ws)[i] = ((const float4*)W)[i];
    __syncthreads();
    int warp = t >> 5, lane = t & 31;
    int base = (blockIdx.x * 8 + warp) * 4;
    float* zr = Zs + warp * 512;
    for (int i = lane; i < 128; i += 32) {
        int r = i >> 5, c = i & 31;
        size_t rowoff = (size_t)idx[base + r] * DD;
        float4 hv = ((const float4*)(hb + rowoff))[c];
        float4 xv = ((const float4*)(xb + rowoff))[c];
        float4 e;
        e.x = 0.5f * (hv.x + xv.x);
        e.y = 0.5f * (hv.y + xv.y);
        e.z = 0.5f * (hv.z + xv.z);
        e.w = 0.5f * (hv.w + xv.w);
        ((float4*)zr)[i] = e;
    }
    __syncwarp();
    float4 bb = ((const float4*)bias)[lane];
    float acc[4][4];
#pragma unroll
    for (int r = 0; r < 4; r++) {
        acc[r][0] = bb.x; acc[r][1] = bb.y; acc[r][2] = bb.z; acc[r][3] = bb.w;
    }
#pragma unroll 4
    for (int k = 0; k < DD; k++) {
        float4 w = *(const float4*)(Ws + k * DD + lane * 4);
        float zv[4];
        zv[0] = zr[k]; zv[1] = zr[DD + k]; zv[2] = zr[2 * DD + k]; zv[3] = zr[3 * DD + k];
#pragma unroll
        for (int r = 0; r < 4; r++) {
            acc[r][0] = fmaf(zv[r], w.x, acc[r][0]);
            acc[r][1] = fmaf(zv[r], w.y, acc[r][1]);
            acc[r][2] = fmaf(zv[r], w.z, acc[r][2]);
            acc[r][3] = fmaf(zv[r], w.w, acc[r][3]);
        }
    }
    float4 g4 = ((const float4*)lng)[lane];
    float4 lb4 = ((const float4*)lnb)[lane];
#pragma unroll
    for (int r = 0; r < 4; r++) {
        float v0 = fmaxf(acc[r][0], 0.f), v1 = fmaxf(acc[r][1], 0.f);
        float v2 = fmaxf(acc[r][2], 0.f), v3 = fmaxf(acc[r][3], 0.f);
        float s = v0 + v1 + v2 + v3;
        for (int o = 16; o; o >>= 1) s += __shfl_xor_sync(0xffffffffu, s, o);
        float mu = s * (1.f / 128.f);
        float w0 = v0 - mu, w1 = v1 - mu, w2 = v2 - mu, w3 = v3 - mu;
        float q = w0 * w0 + w1 * w1 + w2 * w2 + w3 * w3;
        for (int o = 16; o; o >>= 1) q += __shfl_xor_sync(0xffffffffu, q, o);
        float inv = rsqrtf(q * (1.f / 128.f) + 1e-5f);
        float4 ov;
        ov.x = w0 * inv * g4.x + lb4.x;
        ov.y = w1 * inv * g4.y + lb4.y;
        ov.z = w2 * inv * g4.z + lb4.z;
        ov.w = w3 * inv * g4.w + lb4.w;
        *(float4*)(outp + (size_t)(base + r) * DD + lane * 4) = ov;
    }
}

// ------------------------- host orchestration -------------------------------
extern "C" void kernel_launch(void* const* d_in, const int* in_sizes, int n_in,
                              void* d_out, int out_size)
{
    const float* feat_user = (const float*)d_in[0];
    const float* feat_item = (const float*)d_in[1];
    const float* u_W1 = (const float*)d_in[2];
    const float* u_b1 = (const float*)d_in[3];
    const float* u_W2 = (const float*)d_in[4];
    const float* i_W1 = (const float*)d_in[5];
    const float* i_b1 = (const float*)d_in[6];
    const float* i_W2 = (const float*)d_in[7];
    const float* user_W = (const float*)d_in[8];
    const float* user_b = (const float*)d_in[9];
    const float* item_W = (const float*)d_in[10];
    const float* item_b = (const float*)d_in[11];
    const float* ln_g = (const float*)d_in[12];
    const float* ln_b = (const float*)d_in[13];
    const int* mpsrc[4] = {(const int*)d_in[14], (const int*)d_in[16],
                           (const int*)d_in[18], (const int*)d_in[20]};
    const int* mpdst[4] = {(const int*)d_in[15], (const int*)d_in[17],
                           (const int*)d_in[19], (const int*)d_in[21]};
    const int* ui_row = (const int*)d_in[22];
    const int* ui_col = (const int*)d_in[23];
    const int* user_idx = (const int*)d_in[24];
    const int* item_idx = (const int*)d_in[25];
    const int* neg_idx = (const int*)d_in[26];
    float* out = (float*)d_out;

    float *p_h, *p_z, *p_x, *p_rout, *p_rin, *p_dinv;
    int *p_deg, *p_off, *p_cur, *p_csr, *p_cntui, *p_offui, *p_curui, *p_csrui;
    __nv_bfloat16 *p_zh, *p_w1h;
    cudaGetSymbolAddress((void**)&p_h, d_h);
    cudaGetSymbolAddress((void**)&p_z, d_z);
    cudaGetSymbolAddress((void**)&p_zh, d_zh);
    cudaGetSymbolAddress((void**)&p_w1h, d_w1h);
    cudaGetSymbolAddress((void**)&p_x, d_x);
    cudaGetSymbolAddress((void**)&p_rout, d_rout);
    cudaGetSymbolAddress((void**)&p_rin, d_rin);
    cudaGetSymbolAddress((void**)&p_dinv, d_dinv);
    cudaGetSymbolAddress((void**)&p_deg, d_deg);
    cudaGetSymbolAddress((void**)&p_off, d_off);
    cudaGetSymbolAddress((void**)&p_cur, d_cur);
    cudaGetSymbolAddress((void**)&p_csr, d_csr);
    cudaGetSymbolAddress((void**)&p_cntui, d_cntui);
    cudaGetSymbolAddress((void**)&p_offui, d_offui);
    cudaGetSymbolAddress((void**)&p_curui, d_curui);
    cudaGetSymbolAddress((void**)&p_csrui, d_csrui);

    const int T = 256;
    const int GEMM_SMEM = 2 * 128 * SST * 2;
    cudaFuncSetAttribute(k_att2, cudaFuncAttributeMaxDynamicSharedMemorySize, GEMM_SMEM);
    cudaFuncSetAttribute(k_sslgemm_mma, cudaFuncAttributeMaxDynamicSharedMemorySize, GEMM_SMEM);
    cudaFuncSetAttribute(k_final, cudaFuncAttributeMaxDynamicSharedMemorySize, 81920);

    // ---- CSR build ----
    k_zero2<<<(8 * NU + NTOT + T - 1) / T, T>>>(p_deg, 8 * NU, p_cntui, NTOT);
    k_count_all<<<(8 * (EMP / 4) + EUI / 4 + T - 1) / T, T>>>(
        mpsrc[0], mpdst[0], mpsrc[1], mpdst[1],
        mpsrc[2], mpdst[2], mpsrc[3], mpdst[3], ui_row, p_deg, p_cntui);
    k_prep<<<(4 * NU + T - 1) / T, T>>>(p_deg, p_rout, p_rin, p_cntui, p_dinv);
    k_scanA<<<TOT_TILES, 256>>>();
    k_scanB<<<1, 32>>>();
    k_scanC<<<TOT_TILES, 256>>>();
    {
        dim3 gf((EMP + T - 1) / T, 4);
        k_fill_mp<<<gf, T>>>(mpdst[0], mpsrc[0], mpdst[1], mpsrc[1],
                             mpdst[2], mpsrc[2], mpdst[3], mpsrc[3], p_cur, p_csr);
    }
    k_fill<<<(EUI + T - 1) / T, T>>>(ui_row, ui_col, EUI, p_curui, p_csrui);

    // ---- HAN: both sides fused ----
    k_cvtW2<<<(2 * DD * DD + T - 1) / T, T>>>(u_W1, i_W1, p_w1h);
    {
        dim3 gp((NU * 32) / T, 4);
        for (int layer = 0; layer < 3; layer++) {
            const float* h0 = layer ? p_h : feat_user;
            const float* h1 = layer ? p_h + (size_t)NU * DD : feat_item;
            k_pull<<<gp, T>>>(h0, h1, NU, p_rout, p_rin, p_off, p_csr,
                              p_z, p_zh, NU, NU, NU + 1, EMP, NU * DD);
            k_att2<<<4 * ATT_BLOCKS, 256, GEMM_SMEM>>>(u_b1, i_b1, NU);
            k_beta2<<<2, 32>>>(u_W2, i_W2);
            k_combine<<<(NU * DD + T - 1) / T, T>>>(p_z);
        }
    }

    // ---- LightGCN (3 hops, no copies) ----
    float* x0 = p_x;
    float* x1 = p_x + (size_t)NTOT * DD;
    dim3 gu((NTOT * 32) / T, 1);
    k_pull<<<gu, T>>>(feat_user, feat_item, NU, p_dinv, p_dinv, p_offui, p_csrui,
                      x1, (__nv_bfloat16*)0, NTOT, 0, 0, 0, 0);
    k_pull<<<gu, T>>>(x1, x1 + (size_t)NU * DD, NU, p_dinv, p_dinv, p_offui, p_csrui,
                      x0, (__nv_bfloat16*)0, NTOT, 0, 0, 0, 0);
    k_pull<<<gu, T>>>(x0, x0 + (size_t)NU * DD, NU, p_dinv, p_dinv, p_offui, p_csrui,
                      x1, (__nv_bfloat16*)0, NTOT, 0, 0, 0, 0);
    float* xf = x1;

    // ---- SSL (emb fused into k_norm) ----
    {
        dim3 gn((BSZ * 32) / T, 2);
        k_norm<<<gn, T>>>(xf, user_idx, item_idx);
    }
    {
        dim3 gg(BSZ / 128, BSZ / 128, 2);
        k_sslgemm_mma<<<gg, 256, GEMM_SMEM>>>();
    }
    k_sslreduce<<<1, 256>>>(out + (size_t)3 * BSZ * DD, 0.4f / (float)BSZ);

    // ---- final (one launch, 3 jobs; emb fused into gather) ----
    {
        dim3 gfin(BSZ / 32, 3);
        k_final<<<gfin, 256, 81920>>>(xf, user_idx, item_idx, neg_idx,
                                      user_W, user_b, item_W, item_b,
                                      ln_g, ln_b, out);
    }
}